// round 8
// baseline (speedup 1.0000x reference)
#include <cuda_runtime.h>
#include <math.h>
#include <float.h>

#define BB 8
#define CC 64
#define HH 62
#define TT 400
#define HT (HH*TT)            // 24800
#define NTOT (BB*CC*HT)       // 12697600
#define SSZ 32
#define MIDC 4
#define NBLK 194              // ceil(HT/128)

typedef unsigned long long u64;

__device__ __forceinline__ u64 ffma2(u64 a, u64 b, u64 c) {
    u64 d;
    asm("fma.rn.f32x2 %0, %1, %2, %3;" : "=l"(d) : "l"(a), "l"(b), "l"(c));
    return d;
}
__device__ __forceinline__ u64 bcast2(float x) {
    u64 r;
    asm("mov.b64 %0, {%1, %1};" : "=l"(r) : "f"(x));
    return r;
}
__device__ __forceinline__ u64 pack2(float lo, float hi) {
    u64 r;
    asm("mov.b64 %0, {%1, %2};" : "=l"(r) : "f"(lo), "f"(hi));
    return r;
}
__device__ __forceinline__ void unpack2(u64 v, float& lo, float& hi) {
    asm("mov.b64 {%0, %1}, %2;" : "=f"(lo), "=f"(hi) : "l"(v));
}

// ---- tf32 mma helpers -------------------------------------------------------
__device__ __forceinline__ unsigned tf32h(float x) {
    unsigned r; asm("cvt.rna.tf32.f32 %0, %1;" : "=r"(r) : "f"(x)); return r;
}
__device__ __forceinline__ float2 hilo(float x) {
    unsigned h = tf32h(x);
    float hf = __uint_as_float(h);
    return make_float2(hf, __uint_as_float(tf32h(x - hf)));
}
__device__ __forceinline__ void mma_tf32(float* d,
    unsigned a0, unsigned a1, unsigned a2, unsigned a3, unsigned b0, unsigned b1)
{
    asm volatile("mma.sync.aligned.m16n8k8.row.col.f32.tf32.tf32.f32 "
        "{%0,%1,%2,%3}, {%4,%5,%6,%7}, {%8,%9}, {%0,%1,%2,%3};"
        : "+f"(d[0]), "+f"(d[1]), "+f"(d[2]), "+f"(d[3])
        : "r"(a0), "r"(a1), "r"(a2), "r"(a3), "r"(b0), "r"(b1));
}

// ---------------- scratch (device globals) ----------------
__device__ float g_A[NTOT];
__device__ float g_B2[NTOT];
__device__ float g_C2[NTOT];
__device__ float g_D2[NTOT];
__device__ float g_E2[NTOT];
__device__ float g_ach[BB*CC];
__device__ float g_cps[BB*NBLK*CC];
__device__ float g_cpm[BB*NBLK*CC];
__device__ float g_sp[BB*2*HT];
__device__ float g_asp[BB*HT];
__device__ float g_sc[2*TT*CC];
__device__ float g_Wt[8*CC*CC];       // transposed weights [m][c][o]

// ---------------- transpose all 8 pointwise weight matrices --------------------
__global__ void wtrans(const float* __restrict__ in_w, const float* __restrict__ dwpw,
                       const float* __restrict__ d1pw, const float* __restrict__ out_w,
                       float* __restrict__ Wt)
{
    int m = blockIdx.x;
    const float* src = (m == 0) ? in_w
                     : (m < 5)  ? dwpw + (m-1)*CC*CC
                     : (m < 7)  ? d1pw + (m-5)*CC*CC
                                : out_w;
    for (int i = threadIdx.x; i < CC*CC; i += 256) {
        int o = i >> 6, c = i & 63;
        Wt[m*CC*CC + c*CC + o] = src[i];
    }
}

// smem float offsets for mma kernels
#define SXP_PITCH 132               // float2 pitch for sxp rows
#define SWP_PITCH 68                // float2 pitch for sWp rows
#define SWP_OFF   16896             // floats: 64*132*2
#define SRED_OFF  25600             // floats: SWP_OFF + 64*68*2
#define PWM_SMEM  (SRED_OFF*4)              // 102400
#define PWMS_SMEM ((SRED_OFF + 2048)*4)     // 110592
#define CBM_SMEM  (SRED_OFF*4)

// ============ pointwise 64x64 mix via tf32 mma (3xTF32) ======================
// Block 256 thr (8 warps). Tile: 128 pos (M) x 64 out (N), K=64 channels.
// Warp w owns M rows [16w,16w+16). In-place safe (tile fully staged).
template<int ACT, bool SPSTATS, bool CPARTS>
__launch_bounds__(256, 2)
__global__ void pw_mma(const float* __restrict__ in, const float* __restrict__ Wt,
                       const float* __restrict__ gamma, const float* __restrict__ beta,
                       float* __restrict__ out, float* __restrict__ sp,
                       float* __restrict__ cps, float* __restrict__ cpm)
{
    extern __shared__ float sm[];
    float2* sxp = (float2*)sm;                 // [c][pos] hi/lo pairs, pitch 132
    float2* sWp = (float2*)(sm + SWP_OFF);     // [c][o]   hi/lo pairs, pitch 68
    float*  sd  = sm;                          // overlay after mma: [o][pos], pitch 132
    float* sredS = sm + SRED_OFF;
    float* sredM = sredS + 1024;

    int tid = threadIdx.x;
    int b = blockIdx.y;
    int pos0 = blockIdx.x * 128;
    const float* inb = in + (size_t)b*CC*HT;

    // W hi/lo split (Wt is [c][o], coalesced)
    for (int i = tid; i < 4096; i += 256) {
        float w = Wt[i];
        sWp[(i >> 6)*SWP_PITCH + (i & 63)] = hilo(w);
    }
    // x tile hi/lo split
    for (int i = tid; i < 2048; i += 256) {
        int c = i >> 5, j = i & 31;
        int gp = pos0 + j*4;
        float4 v = make_float4(0.f,0.f,0.f,0.f);
        if (gp + 3 < HT) {
            v = *(const float4*)(inb + (size_t)c*HT + gp);
        } else {
            float tmp[4] = {0,0,0,0};
            for (int k = 0; k < 4; k++) if (gp+k < HT) tmp[k] = inb[(size_t)c*HT + gp + k];
            v = make_float4(tmp[0],tmp[1],tmp[2],tmp[3]);
        }
        float vv[4] = {v.x, v.y, v.z, v.w};
        #pragma unroll
        for (int k = 0; k < 4; k++)
            sxp[c*SXP_PITCH + j*4 + k] = hilo(vv[k]);
    }
    __syncthreads();

    int lane = tid & 31, warp = tid >> 5;
    int g = lane >> 2, t4 = lane & 3;
    int m0 = warp * 16;
    float acc[8][4];
    #pragma unroll
    for (int nt = 0; nt < 8; nt++)
        #pragma unroll
        for (int k = 0; k < 4; k++) acc[nt][k] = 0.f;

    #pragma unroll
    for (int kt = 0; kt < 8; kt++) {
        int c0 = kt*8;
        // A fragments (A[m=pos][k=c], row-major m16n8k8 layout)
        float2 A0 = sxp[(c0+t4  )*SXP_PITCH + m0+g  ];
        float2 A1 = sxp[(c0+t4  )*SXP_PITCH + m0+g+8];
        float2 A2 = sxp[(c0+t4+4)*SXP_PITCH + m0+g  ];
        float2 A3 = sxp[(c0+t4+4)*SXP_PITCH + m0+g+8];
        unsigned ah0 = __float_as_uint(A0.x), ah1 = __float_as_uint(A1.x);
        unsigned ah2 = __float_as_uint(A2.x), ah3 = __float_as_uint(A3.x);
        unsigned al0 = __float_as_uint(A0.y), al1 = __float_as_uint(A1.y);
        unsigned al2 = __float_as_uint(A2.y), al3 = __float_as_uint(A3.y);
        #pragma unroll
        for (int nt = 0; nt < 8; nt++) {
            float2 B0 = sWp[(c0+t4  )*SWP_PITCH + nt*8+g];
            float2 B1 = sWp[(c0+t4+4)*SWP_PITCH + nt*8+g];
            unsigned bh0 = __float_as_uint(B0.x), bh1 = __float_as_uint(B1.x);
            unsigned bl0 = __float_as_uint(B0.y), bl1 = __float_as_uint(B1.y);
            mma_tf32(acc[nt], ah0,ah1,ah2,ah3, bh0,bh1);
            mma_tf32(acc[nt], ah0,ah1,ah2,ah3, bl0,bl1);
            mma_tf32(acc[nt], al0,al1,al2,al3, bh0,bh1);
        }
    }
    __syncthreads();   // all reads of sxp done before overlay

    // stage D -> sd[o][pos]
    #pragma unroll
    for (int nt = 0; nt < 8; nt++) {
        int o0 = nt*8 + 2*t4;
        sd[ o0   *SXP_PITCH + m0+g  ] = acc[nt][0];
        sd[(o0+1)*SXP_PITCH + m0+g  ] = acc[nt][1];
        sd[ o0   *SXP_PITCH + m0+g+8] = acc[nt][2];
        sd[(o0+1)*SXP_PITCH + m0+g+8] = acc[nt][3];
    }
    __syncthreads();

    // epilogue
    int px = tid & 31, oy = tid >> 5;
    int p = px*4;
    int gp0 = pos0 + p;
    bool full = (gp0 + 3) < HT;
    float* outb = out + (size_t)b*CC*HT;
    float psum[4] = {0,0,0,0};
    float pmax[4] = {-FLT_MAX,-FLT_MAX,-FLT_MAX,-FLT_MAX};
    #pragma unroll
    for (int o8 = 0; o8 < 8; o8++) {
        int o = oy*8 + o8;
        float4 rv = *(const float4*)(sd + o*SXP_PITCH + p);
        float r[4] = {rv.x, rv.y, rv.z, rv.w};
        if (gamma) {
            float ga = __ldg(gamma + o), be = __ldg(beta + o);
            #pragma unroll
            for (int k = 0; k < 4; k++) r[k] = fmaf(r[k], ga, be);
        }
        #pragma unroll
        for (int k = 0; k < 4; k++) {
            if (ACT == 1) r[k] = fmaxf(r[k], 0.f);
            if (ACT == 2) r[k] = 1.f/(1.f + expf(-r[k]));
        }
        if (SPSTATS) {
            #pragma unroll
            for (int k = 0; k < 4; k++) { psum[k] += r[k]; pmax[k] = fmaxf(pmax[k], r[k]); }
        }
        if (CPARTS) {
            float ps = 0.f, pm = -FLT_MAX;
            #pragma unroll
            for (int k = 0; k < 4; k++)
                if (gp0 + k < HT) { ps += r[k]; pm = fmaxf(pm, r[k]); }
            #pragma unroll
            for (int s = 16; s > 0; s >>= 1) {
                ps += __shfl_xor_sync(0xffffffffu, ps, s);
                pm = fmaxf(pm, __shfl_xor_sync(0xffffffffu, pm, s));
            }
            if (px == 0) {
                cps[((size_t)b*NBLK + blockIdx.x)*CC + o] = ps;
                cpm[((size_t)b*NBLK + blockIdx.x)*CC + o] = pm;
            }
        }
        if (full) {
            *(float4*)(outb + (size_t)o*HT + gp0) = make_float4(r[0],r[1],r[2],r[3]);
        } else {
            for (int k = 0; k < 4; k++) if (gp0+k < HT) outb[(size_t)o*HT + gp0 + k] = r[k];
        }
    }

    if (SPSTATS) {
        #pragma unroll
        for (int k = 0; k < 4; k++) { sredS[oy*128 + p + k] = psum[k]; sredM[oy*128 + p + k] = pmax[k]; }
        __syncthreads();
        if (tid < 128) {
            float s = 0.f, m = -FLT_MAX;
            #pragma unroll
            for (int gq = 0; gq < 8; gq++) { s += sredS[gq*128 + tid]; m = fmaxf(m, sredM[gq*128 + tid]); }
            int gp = pos0 + tid;
            if (gp < HT) {
                sp[(size_t)b*2*HT + gp]      = s*(1.f/CC);
                sp[(size_t)b*2*HT + HT + gp] = m;
            }
        }
    }
}

// ============ fused dw1x3(b1^2 * a_ch) + pointwise(mma) + bn + sigmoid =======
__launch_bounds__(256, 2)
__global__ void cb_mma(const float* __restrict__ b1, const float* __restrict__ ach,
                       const float* __restrict__ dw, const float* __restrict__ Wt,
                       const float* __restrict__ gamma, const float* __restrict__ beta,
                       float* __restrict__ out)
{
    extern __shared__ float sm[];
    float2* sxp = (float2*)sm;
    float2* sWp = (float2*)(sm + SWP_OFF);
    float*  sd  = sm;

    int tid = threadIdx.x;
    int b = blockIdx.y;
    int pos0 = blockIdx.x * 128;
    const float* inb = b1 + (size_t)b*CC*HT;

    for (int i = tid; i < 4096; i += 256)
        sWp[(i >> 6)*SWP_PITCH + (i & 63)] = hilo(Wt[i]);

    // dw1x3 on (v^2 * a) computed from 3 L1-cached global reads per element
    for (int i = tid; i < 8192; i += 256) {
        int c = i >> 7, j = i & 127;
        int gp = pos0 + j;
        float r = 0.f;
        if (gp < HT) {
            int t = gp - (gp/TT)*TT;
            float a  = __ldg(ach + b*CC + c);
            float w0 = __ldg(dw + c*3), w1 = __ldg(dw + c*3 + 1), w2 = __ldg(dw + c*3 + 2);
            const float* row = inb + (size_t)c*HT;
            float v0 = row[gp];
            r = w1 * (v0*v0*a);
            if (t > 0)    { float vm = row[gp-1]; r = fmaf(w0, vm*vm*a, r); }
            if (t < TT-1) { float vp = row[gp+1]; r = fmaf(w2, vp*vp*a, r); }
        }
        sxp[c*SXP_PITCH + j] = hilo(r);
    }
    __syncthreads();

    int lane = tid & 31, warp = tid >> 5;
    int g = lane >> 2, t4 = lane & 3;
    int m0 = warp * 16;
    float acc[8][4];
    #pragma unroll
    for (int nt = 0; nt < 8; nt++)
        #pragma unroll
        for (int k = 0; k < 4; k++) acc[nt][k] = 0.f;

    #pragma unroll
    for (int kt = 0; kt < 8; kt++) {
        int c0 = kt*8;
        float2 A0 = sxp[(c0+t4  )*SXP_PITCH + m0+g  ];
        float2 A1 = sxp[(c0+t4  )*SXP_PITCH + m0+g+8];
        float2 A2 = sxp[(c0+t4+4)*SXP_PITCH + m0+g  ];
        float2 A3 = sxp[(c0+t4+4)*SXP_PITCH + m0+g+8];
        unsigned ah0 = __float_as_uint(A0.x), ah1 = __float_as_uint(A1.x);
        unsigned ah2 = __float_as_uint(A2.x), ah3 = __float_as_uint(A3.x);
        unsigned al0 = __float_as_uint(A0.y), al1 = __float_as_uint(A1.y);
        unsigned al2 = __float_as_uint(A2.y), al3 = __float_as_uint(A3.y);
        #pragma unroll
        for (int nt = 0; nt < 8; nt++) {
            float2 B0 = sWp[(c0+t4  )*SWP_PITCH + nt*8+g];
            float2 B1 = sWp[(c0+t4+4)*SWP_PITCH + nt*8+g];
            unsigned bh0 = __float_as_uint(B0.x), bh1 = __float_as_uint(B1.x);
            unsigned bl0 = __float_as_uint(B0.y), bl1 = __float_as_uint(B1.y);
            mma_tf32(acc[nt], ah0,ah1,ah2,ah3, bh0,bh1);
            mma_tf32(acc[nt], ah0,ah1,ah2,ah3, bl0,bl1);
            mma_tf32(acc[nt], al0,al1,al2,al3, bh0,bh1);
        }
    }
    __syncthreads();

    #pragma unroll
    for (int nt = 0; nt < 8; nt++) {
        int o0 = nt*8 + 2*t4;
        sd[ o0   *SXP_PITCH + m0+g  ] = acc[nt][0];
        sd[(o0+1)*SXP_PITCH + m0+g  ] = acc[nt][1];
        sd[ o0   *SXP_PITCH + m0+g+8] = acc[nt][2];
        sd[(o0+1)*SXP_PITCH + m0+g+8] = acc[nt][3];
    }
    __syncthreads();

    int px = tid & 31, oy = tid >> 5;
    int p = px*4;
    int gp0 = pos0 + p;
    bool full = (gp0 + 3) < HT;
    float* outb = out + (size_t)b*CC*HT;
    #pragma unroll
    for (int o8 = 0; o8 < 8; o8++) {
        int o = oy*8 + o8;
        float4 rv = *(const float4*)(sd + o*SXP_PITCH + p);
        float ga = __ldg(gamma + o), be = __ldg(beta + o);
        float r[4] = {rv.x, rv.y, rv.z, rv.w};
        #pragma unroll
        for (int k = 0; k < 4; k++) {
            r[k] = fmaf(r[k], ga, be);
            r[k] = 1.f/(1.f + expf(-r[k]));
        }
        if (full) *(float4*)(outb + (size_t)o*HT + gp0) = make_float4(r[0],r[1],r[2],r[3]);
        else for (int k = 0; k < 4; k++) if (gp0+k < HT) outb[(size_t)o*HT + gp0 + k] = r[k];
    }
}

// ========= dual depthwise 5x5: 64t x 16h tiles, 4 outputs/thread, f32x2 ========
__launch_bounds__(256)
__global__ void dw5_dual2(const float* __restrict__ in, const float* __restrict__ w0,
                          const float* __restrict__ w1,
                          float* __restrict__ out0, float* __restrict__ out1, int rev)
{
    int bc = blockIdx.z;
    int c  = bc & (CC-1);
    __shared__ float tile[20*68];
    __shared__ u64 swp[25];
    int t0 = blockIdx.x*64 - 2;
    int h0 = blockIdx.y*16 - 2;
    const float* base = in + (size_t)bc*HT;
    int tid = threadIdx.x;

    if (tid < 25) swp[tid] = pack2(__ldg(w0 + c*25 + tid), __ldg(w1 + c*25 + tid));

    for (int i = tid; i < 20*68; i += 256) {
        int hh = i / 68, tt = i - hh*68;
        int h = h0 + hh, t = t0 + tt;
        float v = 0.f;
        if (h >= 0 && h < HH && t >= 0 && t < TT) {
            int tr = rev ? (TT-1-t) : t;
            v = base[h*TT + tr];
        }
        tile[i] = v;
    }
    __syncthreads();

    int tt0 = (tid & 15)*4;
    int hh  = tid >> 4;
    int tg  = blockIdx.x*64 + tt0;
    int hg  = blockIdx.y*16 + hh;

    u64 acc[4] = {0ull, 0ull, 0ull, 0ull};
    #pragma unroll
    for (int kh = 0; kh < 5; kh++) {
        const float* row = tile + (hh + kh)*68 + tt0;
        float4 ra = *(const float4*)(row);
        float4 rb = *(const float4*)(row + 4);
        float r[8] = {ra.x, ra.y, ra.z, ra.w, rb.x, rb.y, rb.z, rb.w};
        #pragma unroll
        for (int kw = 0; kw < 5; kw++) {
            u64 w = swp[kh*5 + kw];
            acc[0] = ffma2(w, bcast2(r[kw+0]), acc[0]);
            acc[1] = ffma2(w, bcast2(r[kw+1]), acc[1]);
            acc[2] = ffma2(w, bcast2(r[kw+2]), acc[2]);
            acc[3] = ffma2(w, bcast2(r[kw+3]), acc[3]);
        }
    }

    if (hg >= HH) return;
    float o0[4], o1[4];
    #pragma unroll
    for (int k = 0; k < 4; k++) unpack2(acc[k], o0[k], o1[k]);
    size_t obase = (size_t)bc*HT + hg*TT + tg;
    if (tg + 3 < TT) {
        *(float4*)(out0 + obase) = make_float4(o0[0], o0[1], o0[2], o0[3]);
        *(float4*)(out1 + obase) = make_float4(o1[0], o1[1], o1[2], o1[3]);
    } else {
        for (int k = 0; k < 4; k++) if (tg + k < TT) {
            out0[obase + k] = o0[k];
            out1[obase + k] = o1[k];
        }
    }
}

// ---------------- channel attention: reduce partials + MLP ---------------------
__global__ void chan_attn2(const float* __restrict__ cps, const float* __restrict__ cpm,
                           const float* __restrict__ w1, const float* __restrict__ w2,
                           float* __restrict__ a)
{
    int b = blockIdx.x, tid = threadIdx.x;
    __shared__ float sa[CC], smx[CC], hs[MIDC];
    int c = tid >> 2, q = tid & 3;
    float s = 0.f, m = -FLT_MAX;
    for (int k = q; k < NBLK; k += 4) {
        s += cps[((size_t)b*NBLK + k)*CC + c];
        m = fmaxf(m, cpm[((size_t)b*NBLK + k)*CC + c]);
    }
    s += __shfl_xor_sync(0xffffffffu, s, 1);
    m = fmaxf(m, __shfl_xor_sync(0xffffffffu, m, 1));
    s += __shfl_xor_sync(0xffffffffu, s, 2);
    m = fmaxf(m, __shfl_xor_sync(0xffffffffu, m, 2));
    if (q == 0) { sa[c] = s*(1.f/(float)HT); smx[c] = m; }
    __syncthreads();
    if (tid < MIDC) {
        float ha = 0.f, hm = 0.f;
        for (int k = 0; k < CC; k++) {
            ha = fmaf(sa[k],  w1[tid*CC + k], ha);
            hm = fmaf(smx[k], w1[tid*CC + k], hm);
        }
        hs[tid] = fmaxf(ha, 0.f) + fmaxf(hm, 0.f);
    }
    __syncthreads();
    if (tid < CC) {
        float acc = 0.f;
        #pragma unroll
        for (int j = 0; j < MIDC; j++) acc = fmaf(hs[j], w2[tid*MIDC + j], acc);
        a[b*CC + tid] = 1.f/(1.f + expf(-acc));
    }
}

// ---------------- spatial attention 7x7 conv (2ch->1) + sigmoid -----------------
__global__ void spat_conv(const float* __restrict__ sp, const float* __restrict__ w,
                          float* __restrict__ asp)
{
    int t = blockIdx.x*32 + threadIdx.x;
    int h = blockIdx.y*8  + threadIdx.y;
    int b = blockIdx.z;
    if (t >= TT || h >= HH) return;
    float acc = 0.f;
    #pragma unroll
    for (int ci = 0; ci < 2; ci++) {
        const float* base = sp + ((size_t)b*2 + ci)*HT;
        #pragma unroll
        for (int kh = 0; kh < 7; kh++) {
            int hh = h + kh - 3;
            if (hh < 0 || hh >= HH) continue;
            #pragma unroll
            for (int kw = 0; kw < 7; kw++) {
                int tt = t + kw - 3;
                if (tt < 0 || tt >= TT) continue;
                acc = fmaf(base[hh*TT + tt], __ldg(&w[ci*49 + kh*7 + kw]), acc);
            }
        }
    }
    asp[(size_t)b*HT + h*TT + t] = 1.f/(1.f + expf(-acc));
}

// ---------------- SSM precompute: log-depth chain via A^8 ----------------------
#define SSM_SMEM ((5152 + TT*SSZ)*4)
__launch_bounds__(256)
__global__ void ssm_pre3(const float* __restrict__ A, const float* __restrict__ Bv,
                         const float* __restrict__ Cm, float* __restrict__ sc)
{
    extern __shared__ float sm[];
    float* sA  = sm;
    float* sM  = sm + 1024;
    float* sT  = sm + 2048;
    float* sC  = sm + 3072;
    float* sVV = sm + 5120;
    float* sS  = sm + 5152;

    int half = blockIdx.x;
    A  += half*SSZ*SSZ;
    Bv += half*SSZ;
    Cm += half*SSZ*CC;
    sc += (size_t)half*TT*CC;

    int tid = threadIdx.x;
    int wid = tid >> 5, lid = tid & 31;

    for (int i = tid; i < 1024; i += 256) sA[i] = A[i];
    for (int i = tid; i < 2048; i += 256) sC[i] = Cm[i];
    __syncthreads();
    for (int i = tid; i < 1024; i += 256) {
        int r = i >> 5, c = i & 31;
        float acc = 0.f;
        #pragma unroll
        for (int k = 0; k < 32; k++) acc = fmaf(sA[r*32+k], sA[k*32+c], acc);
        sT[i] = acc;
    }
    __syncthreads();
    for (int i = tid; i < 1024; i += 256) {
        int r = i >> 5, c = i & 31;
        float acc = 0.f;
        #pragma unroll
        for (int k = 0; k < 32; k++) acc = fmaf(sT[r*32+k], sT[k*32+c], acc);
        sM[i] = acc;
    }
    __syncthreads();
    for (int i = tid; i < 1024; i += 256) {
        int r = i >> 5, c = i & 31;
        float acc = 0.f;
        #pragma unroll
        for (int k = 0; k < 32; k++) acc = fmaf(sM[r*32+k], sM[k*32+c], acc);
        sT[i] = acc;
    }
    __syncthreads();

    if (wid == 0) {
        float bv = Bv[lid];
        float Arow[32];
        #pragma unroll
        for (int j = 0; j < 32; j++) Arow[j] = sA[lid*32 + j];
        float x = bv;
        sS[lid] = x;
        #pragma unroll
        for (int k = 1; k < 8; k++) {
            float nx = bv;
            #pragma unroll
            for (int j = 0; j < 32; j++) nx = fmaf(__shfl_sync(0xffffffffu, x, j), Arow[j], nx);
            x = nx;
            sS[k*32 + lid] = x;
        }
        sVV[lid] = x;
    }
    __syncthreads();

    {
        float Mrow[32];
        #pragma unroll
        for (int j = 0; j < 32; j++) Mrow[j] = sT[lid*32 + j];
        float vv = sVV[lid];
        float x = sS[wid*32 + lid];
        for (int n = 1; n < 50; n++) {
            float p0 = vv, p1 = 0.f, p2 = 0.f, p3 = 0.f;
            #pragma unroll
            for (int j = 0; j < 8; j++) {
                p0 = fmaf(__shfl_sync(0xffffffffu, x, j),    Mrow[j],    p0);
                p1 = fmaf(__shfl_sync(0xffffffffu, x, j+8),  Mrow[j+8],  p1);
                p2 = fmaf(__shfl_sync(0xffffffffu, x, j+16), Mrow[j+16], p2);
                p3 = fmaf(__shfl_sync(0xffffffffu, x, j+24), Mrow[j+24], p3);
            }
            x = (p0 + p1) + (p2 + p3);
            sS[(wid + 8*n)*32 + lid] = x;
        }
    }
    __syncthreads();

    for (int i = tid; i < TT*CC; i += 256) {
        int t = i >> 6, c = i & 63;
        float acc = 0.f;
        #pragma unroll
        for (int k = 0; k < 32; k++) acc = fmaf(sS[t*32 + k], sC[k*64 + c], acc);
        sc[i] = acc;
    }
}

// ---------------- fused: residual-gelu + channel-LN + spatial gate --------------
__launch_bounds__(256)
__global__ void final_fuse(const float* __restrict__ cb, const float* __restrict__ b2,
                           const float* __restrict__ asp, const float* __restrict__ sc,
                           const float* __restrict__ Dv, const float* __restrict__ lg,
                           const float* __restrict__ lb, float* __restrict__ out, int revout)
{
    __shared__ float sred[256];
    __shared__ float smu[32], srs[32];
    __shared__ float sD[CC], slg[CC], slb[CC];

    int tid = threadIdx.x;
    int px = tid & 31, cy = tid >> 5;
    int b = blockIdx.y;
    int pos = blockIdx.x*32 + px;
    if (tid < CC) { sD[tid] = Dv[tid]; slg[tid] = lg[tid]; slb[tid] = lb[tid]; }
    __syncthreads();

    int t = pos % TT, h = pos / TT;
    const float* cbb = cb + (size_t)b*CC*HT + pos;
    const float* b2b = b2 + (size_t)b*CC*HT + pos;
    const float* scp = sc + t*CC;

    float val[8], bvv[8];
    float sum = 0.f;
    #pragma unroll
    for (int k = 0; k < 8; k++) {
        int c = cy*8 + k;
        int c2 = (h - 2*c) & (CC-1);
        float x = cbb[(size_t)c*HT];
        bvv[k] = b2b[(size_t)c*HT];
        float pre = __ldg(scp + c2) + x*sD[c2];
        float gel = 0.5f*pre*(1.f + erff(pre*0.70710678118654752f));
        val[k] = x + gel;
        sum += val[k];
    }
    sred[cy*32 + px] = sum;
    __syncthreads();
    if (cy == 0) {
        float tot = 0.f;
        #pragma unroll
        for (int g = 0; g < 8; g++) tot += sred[g*32 + px];
        smu[px] = tot*(1.f/CC);
    }
    __syncthreads();
    float mu = smu[px];
    float vp = 0.f;
    #pragma unroll
    for (int k = 0; k < 8; k++) { float d = val[k]-mu; vp = fmaf(d, d, vp); }
    __syncthreads();
    sred[cy*32 + px] = vp;
    __syncthreads();
    if (cy == 0) {
        float tot = 0.f;
        #pragma unroll
        for (int g = 0; g < 8; g++) tot += sred[g*32 + px];
        srs[px] = rsqrtf(tot*(1.f/CC) + 1e-5f);
    }
    __syncthreads();
    float rstd = srs[px];
    float aspv = asp[(size_t)b*HT + pos];
    int opos = revout ? (h*TT + (TT-1-t)) : pos;
    float* outb = out + (size_t)b*CC*HT + opos;
    #pragma unroll
    for (int k = 0; k < 8; k++) {
        int c = cy*8 + k;
        float y = (val[k]-mu)*rstd*slg[c] + slb[c];
        float sb = 1.f/(1.f + expf(-(bvv[k]*bvv[k]*aspv)));
        outb[(size_t)c*HT] = y*sb;
    }
}

// ---------------- host orchestration --------------------------------------------
static void run_half(const float* in, float* outb, int rev,
                     const float* dwdw, const float* Wt_b1, const float* Wt_b2,
                     const float* dwg, const float* dwb,
                     const float* caw1, const float* caw2, const float* saw,
                     const float* d1dw, const float* Wt_cb, const float* d1g, const float* d1b,
                     const float* sD, const float* lng, const float* lnb,
                     const float* psc_half,
                     float* bufB, float* bufC, float* bufD,
                     float* pach, float* pcps, float* pcpm, float* psp, float* pasp)
{
    dim3 g5((TT+63)/64, (HH+15)/16, BB*CC);
    dw5_dual2<<<g5, 256>>>(in, dwdw, dwdw + CC*25, bufB, bufC, rev);

    dim3 gp(NBLK, BB);
    pw_mma<1,false,true ><<<gp, 256, PWM_SMEM>>>(bufB, Wt_b1, dwg,    dwb,    bufB, nullptr, pcps, pcpm);
    pw_mma<1,true ,false><<<gp, 256, PWMS_SMEM>>>(bufC, Wt_b2, dwg+CC, dwb+CC, bufC, psp, nullptr, nullptr);

    chan_attn2<<<BB, 256>>>(pcps, pcpm, caw1, caw2, pach);

    cb_mma<<<gp, 256, CBM_SMEM>>>(bufB, pach, d1dw, Wt_cb, d1g, d1b, bufD);

    spat_conv<<<dim3((TT+31)/32, (HH+7)/8, BB), dim3(32, 8)>>>(psp, saw, pasp);

    final_fuse<<<dim3(HT/32, BB), 256>>>(bufD, bufC, pasp, psc_half, sD, lng, lnb, outb, rev);
}

extern "C" void kernel_launch(void* const* d_in, const int* in_sizes, int n_in,
                              void* d_out, int out_size)
{
    const float* x       = (const float*)d_in[0];
    const float* in_w    = (const float*)d_in[1];
    const float* dw2d_dw = (const float*)d_in[2];
    const float* dw2d_pw = (const float*)d_in[3];
    const float* dw2d_g  = (const float*)d_in[4];
    const float* dw2d_b  = (const float*)d_in[5];
    const float* ca_w1   = (const float*)d_in[6];
    const float* ca_w2   = (const float*)d_in[7];
    const float* sa_w    = (const float*)d_in[8];
    const float* dw1d_dw = (const float*)d_in[9];
    const float* dw1d_pw = (const float*)d_in[10];
    const float* dw1d_g  = (const float*)d_in[11];
    const float* dw1d_b  = (const float*)d_in[12];
    const float* ssm_A   = (const float*)d_in[13];
    const float* ssm_B   = (const float*)d_in[14];
    const float* ssm_C   = (const float*)d_in[15];
    const float* ssm_D   = (const float*)d_in[16];
    const float* ln_g    = (const float*)d_in[17];
    const float* ln_b    = (const float*)d_in[18];
    const float* out_w   = (const float*)d_in[19];
    const float* out_g   = (const float*)d_in[20];
    const float* out_b   = (const float*)d_in[21];

    float *pA, *pB, *pC, *pD, *pE, *pach, *pcps, *pcpm, *psp, *pasp, *psc, *pWt;
    cudaGetSymbolAddress((void**)&pA,   g_A);
    cudaGetSymbolAddress((void**)&pB,   g_B2);
    cudaGetSymbolAddress((void**)&pC,   g_C2);
    cudaGetSymbolAddress((void**)&pD,   g_D2);
    cudaGetSymbolAddress((void**)&pE,   g_E2);
    cudaGetSymbolAddress((void**)&pach, g_ach);
    cudaGetSymbolAddress((void**)&pcps, g_cps);
    cudaGetSymbolAddress((void**)&pcpm, g_cpm);
    cudaGetSymbolAddress((void**)&psp,  g_sp);
    cudaGetSymbolAddress((void**)&pasp, g_asp);
    cudaGetSymbolAddress((void**)&psc,  g_sc);
    cudaGetSymbolAddress((void**)&pWt,  g_Wt);

    cudaFuncSetAttribute(pw_mma<0,false,false>, cudaFuncAttributeMaxDynamicSharedMemorySize, PWM_SMEM);
    cudaFuncSetAttribute(pw_mma<1,false,false>, cudaFuncAttributeMaxDynamicSharedMemorySize, PWM_SMEM);
    cudaFuncSetAttribute(pw_mma<1,false,true >, cudaFuncAttributeMaxDynamicSharedMemorySize, PWM_SMEM);
    cudaFuncSetAttribute(pw_mma<1,true ,false>, cudaFuncAttributeMaxDynamicSharedMemorySize, PWMS_SMEM);
    cudaFuncSetAttribute(cb_mma,                cudaFuncAttributeMaxDynamicSharedMemorySize, CBM_SMEM);
    cudaFuncSetAttribute(ssm_pre3,              cudaFuncAttributeMaxDynamicSharedMemorySize, SSM_SMEM);

    wtrans<<<8, 256>>>(in_w, dw2d_pw, dw1d_pw, out_w, pWt);
    ssm_pre3<<<2, 256, SSM_SMEM>>>(ssm_A, ssm_B, ssm_C, psc);

    dim3 gp(NBLK, BB);

    // input pointwise mix
    pw_mma<0,false,false><<<gp, 256, PWM_SMEM>>>(x, pWt, nullptr, nullptr, pA, nullptr, nullptr, nullptr);

    // half 1
    run_half(pA, pE, 0,
             dw2d_dw, pWt + 1*CC*CC, pWt + 2*CC*CC, dw2d_g, dw2d_b,
             ca_w1, ca_w2, sa_w,
             dw1d_dw, pWt + 5*CC*CC, dw1d_g, dw1d_b,
             ssm_D, ln_g, ln_b, psc,
             pB, pC, pD, pach, pcps, pcpm, psp, pasp);

    // half 2 (reversed read, reversed write-back)
    run_half(pE, pA, 1,
             dw2d_dw + 2*CC*25, pWt + 3*CC*CC, pWt + 4*CC*CC, dw2d_g + 2*CC, dw2d_b + 2*CC,
             ca_w1 + MIDC*CC, ca_w2 + CC*MIDC, sa_w + 2*49,
             dw1d_dw + CC*3, pWt + 6*CC*CC, dw1d_g + CC, dw1d_b + CC,
             ssm_D + CC, ln_g + CC, ln_b + CC, psc + TT*CC,
             pB, pC, pD, pach, pcps, pcpm, psp, pasp);

    // output pointwise mix + bn + relu
    pw_mma<1,false,false><<<gp, 256, PWM_SMEM>>>(pA, pWt + 7*CC*CC, out_g, out_b, (float*)d_out, nullptr, nullptr, nullptr);
}

// round 9
// speedup vs baseline: 1.4293x; 1.4293x over previous
#include <cuda_runtime.h>
#include <math.h>
#include <float.h>

#define BB 8
#define CC 64
#define HH 62
#define TT 400
#define HT (HH*TT)            // 24800
#define NTOT (BB*CC*HT)       // 12697600
#define SSZ 32
#define MIDC 4
#define NBLK 194              // ceil(HT/128)

typedef unsigned long long u64;

__device__ __forceinline__ u64 ffma2(u64 a, u64 b, u64 c) {
    u64 d;
    asm("fma.rn.f32x2 %0, %1, %2, %3;" : "=l"(d) : "l"(a), "l"(b), "l"(c));
    return d;
}
__device__ __forceinline__ u64 bcast2(float x) {
    u64 r;
    asm("mov.b64 %0, {%1, %1};" : "=l"(r) : "f"(x));
    return r;
}
__device__ __forceinline__ u64 pack2(float lo, float hi) {
    u64 r;
    asm("mov.b64 %0, {%1, %2};" : "=l"(r) : "f"(lo), "f"(hi));
    return r;
}
__device__ __forceinline__ void unpack2(u64 v, float& lo, float& hi) {
    asm("mov.b64 {%0, %1}, %2;" : "=f"(lo), "=f"(hi) : "l"(v));
}

// ---------------- scratch (device globals) ----------------
__device__ float g_A[NTOT];
__device__ float g_B2[NTOT];
__device__ float g_C2[NTOT];
__device__ float g_D2[NTOT];
__device__ float g_E2[NTOT];
__device__ float g_ach[BB*CC];
__device__ float g_cps[BB*NBLK*CC];
__device__ float g_cpm[BB*NBLK*CC];
__device__ float g_sp[BB*2*HT];
__device__ float g_asp[BB*HT];
__device__ float g_sc[2*TT*CC];
__device__ float g_Wt[8*CC*CC];       // transposed weights [m][c][o]

// ---------------- transpose all 8 pointwise weight matrices --------------------
__global__ void wtrans(const float* __restrict__ in_w, const float* __restrict__ dwpw,
                       const float* __restrict__ d1pw, const float* __restrict__ out_w,
                       float* __restrict__ Wt)
{
    int m = blockIdx.x;
    const float* src = (m == 0) ? in_w
                     : (m < 5)  ? dwpw + (m-1)*CC*CC
                     : (m < 7)  ? d1pw + (m-5)*CC*CC
                                : out_w;
    for (int i = threadIdx.x; i < CC*CC; i += 256) {
        int o = i >> 6, c = i & 63;
        Wt[m*CC*CC + c*CC + o] = src[i];
    }
}

// ---- shared f32x2 GEMM core (64 outs x 128 pos, K=64), used by all pw kernels --
// Requires: sWt [c][o] 4096 floats, sx [c][128 pos]. Thread tid: px=tid&31, oy=tid>>5.
// Produces rr[8][4]: 8 outs (oy*8+o8) x 4 positions (px*4+k).
__device__ __forceinline__ void gemm_core(const float* sWt, const float* sx,
                                          int px, int oy, float rr[8][4])
{
    int p = px*4;
    u64 acc2[4][4];
    #pragma unroll
    for (int q = 0; q < 4; q++)
        #pragma unroll
        for (int k = 0; k < 4; k++) acc2[q][k] = 0ull;

    #pragma unroll
    for (int c4 = 0; c4 < 16; c4++) {
        #pragma unroll
        for (int cc = 0; cc < 4; cc++) {
            int c = c4*4 + cc;
            float4 xv = *(const float4*)(sx + c*128 + p);
            u64 xp0 = bcast2(xv.x), xp1 = bcast2(xv.y);
            u64 xp2 = bcast2(xv.z), xp3 = bcast2(xv.w);
            const ulonglong2* wrow = (const ulonglong2*)(sWt + c*64 + oy*8);
            ulonglong2 wa = wrow[0];
            ulonglong2 wb = wrow[1];
            acc2[0][0] = ffma2(wa.x, xp0, acc2[0][0]);
            acc2[0][1] = ffma2(wa.x, xp1, acc2[0][1]);
            acc2[0][2] = ffma2(wa.x, xp2, acc2[0][2]);
            acc2[0][3] = ffma2(wa.x, xp3, acc2[0][3]);
            acc2[1][0] = ffma2(wa.y, xp0, acc2[1][0]);
            acc2[1][1] = ffma2(wa.y, xp1, acc2[1][1]);
            acc2[1][2] = ffma2(wa.y, xp2, acc2[1][2]);
            acc2[1][3] = ffma2(wa.y, xp3, acc2[1][3]);
            acc2[2][0] = ffma2(wb.x, xp0, acc2[2][0]);
            acc2[2][1] = ffma2(wb.x, xp1, acc2[2][1]);
            acc2[2][2] = ffma2(wb.x, xp2, acc2[2][2]);
            acc2[2][3] = ffma2(wb.x, xp3, acc2[2][3]);
            acc2[3][0] = ffma2(wb.y, xp0, acc2[3][0]);
            acc2[3][1] = ffma2(wb.y, xp1, acc2[3][1]);
            acc2[3][2] = ffma2(wb.y, xp2, acc2[3][2]);
            acc2[3][3] = ffma2(wb.y, xp3, acc2[3][3]);
        }
    }
    #pragma unroll
    for (int q = 0; q < 4; q++)
        #pragma unroll
        for (int k = 0; k < 4; k++)
            unpack2(acc2[q][k], rr[2*q][k], rr[2*q+1][k]);
}

// ============ plain pointwise 64x64 mix (in/out mixes), f32x2 =================
// ACT: 0=none, 1=relu. In-place safe (tile fully staged).
template<int ACT>
__launch_bounds__(256, 3)
__global__ void pw2(const float* __restrict__ in, const float* __restrict__ Wt,
                    const float* __restrict__ gamma, const float* __restrict__ beta,
                    float* __restrict__ out)
{
    extern __shared__ float sm[];
    float* sWt = sm;                   // 4096 floats, [c][o]
    float* sx  = sm + 4096;            // 64*128 floats

    int tid = threadIdx.x;
    int px = tid & 31, oy = tid >> 5;
    int b = blockIdx.y;
    int pos0 = blockIdx.x * 128;
    const float* inb = in + (size_t)b*CC*HT;

    #pragma unroll
    for (int i = tid; i < 1024; i += 256)
        ((float4*)sWt)[i] = ((const float4*)Wt)[i];

    #pragma unroll
    for (int i = tid; i < 2048; i += 256) {
        int c = i >> 5, j = i & 31;
        int gp = pos0 + j*4;
        float4 v = make_float4(0.f,0.f,0.f,0.f);
        if (gp + 3 < HT) {
            v = *(const float4*)(inb + (size_t)c*HT + gp);
        } else {
            float tmp[4] = {0,0,0,0};
            for (int k = 0; k < 4; k++) if (gp+k < HT) tmp[k] = inb[(size_t)c*HT + gp + k];
            v = make_float4(tmp[0],tmp[1],tmp[2],tmp[3]);
        }
        *(float4*)(sx + c*128 + j*4) = v;
    }
    __syncthreads();

    float rr[8][4];
    gemm_core(sWt, sx, px, oy, rr);

    int gp0 = pos0 + px*4;
    bool full = (gp0 + 3) < HT;
    float* outb = out + (size_t)b*CC*HT;
    #pragma unroll
    for (int o8 = 0; o8 < 8; o8++) {
        int o = oy*8 + o8;
        float r[4];
        #pragma unroll
        for (int k = 0; k < 4; k++) r[k] = rr[o8][k];
        if (gamma) {
            float g = __ldg(gamma + o), be = __ldg(beta + o);
            #pragma unroll
            for (int k = 0; k < 4; k++) r[k] = fmaf(r[k], g, be);
        }
        if (ACT == 1) {
            #pragma unroll
            for (int k = 0; k < 4; k++) r[k] = fmaxf(r[k], 0.f);
        }
        if (full) {
            *(float4*)(outb + (size_t)o*HT + gp0) = make_float4(r[0],r[1],r[2],r[3]);
        } else {
            for (int k = 0; k < 4; k++) if (gp0+k < HT) outb[(size_t)o*HT + gp0 + k] = r[k];
        }
    }
}

// ============ merged branch pw: z=0 -> b1 (+chan partials), z=1 -> b2 (+spat) ==
__launch_bounds__(256, 3)
__global__ void pw_dual(const float* __restrict__ b1in, const float* __restrict__ b2in,
                        const float* __restrict__ Wt1, const float* __restrict__ Wt2,
                        const float* __restrict__ gamma, const float* __restrict__ beta,
                        float* __restrict__ out1, float* __restrict__ out2,
                        float* __restrict__ sp, float* __restrict__ cps, float* __restrict__ cpm)
{
    extern __shared__ float sm[];
    float* sWt = sm;                   // 4096
    float* sx  = sm + 4096;            // 8192
    float* sredS = sm + 4096 + 8192;   // 1024 (branch 1)
    float* sredM = sredS + 1024;       // 1024

    int branch = blockIdx.z;
    const float* in  = branch ? b2in : b1in;
    const float* Wt  = branch ? Wt2  : Wt1;
    const float* gam = gamma + branch*CC;
    const float* bet = beta  + branch*CC;
    float* out = branch ? out2 : out1;

    int tid = threadIdx.x;
    int px = tid & 31, oy = tid >> 5;
    int b = blockIdx.y;
    int pos0 = blockIdx.x * 128;
    const float* inb = in + (size_t)b*CC*HT;

    #pragma unroll
    for (int i = tid; i < 1024; i += 256)
        ((float4*)sWt)[i] = ((const float4*)Wt)[i];

    #pragma unroll
    for (int i = tid; i < 2048; i += 256) {
        int c = i >> 5, j = i & 31;
        int gp = pos0 + j*4;
        float4 v = make_float4(0.f,0.f,0.f,0.f);
        if (gp + 3 < HT) {
            v = *(const float4*)(inb + (size_t)c*HT + gp);
        } else {
            float tmp[4] = {0,0,0,0};
            for (int k = 0; k < 4; k++) if (gp+k < HT) tmp[k] = inb[(size_t)c*HT + gp + k];
            v = make_float4(tmp[0],tmp[1],tmp[2],tmp[3]);
        }
        *(float4*)(sx + c*128 + j*4) = v;
    }
    __syncthreads();

    float rr[8][4];
    gemm_core(sWt, sx, px, oy, rr);

    int gp0 = pos0 + px*4;
    bool full = (gp0 + 3) < HT;
    float* outb = out + (size_t)b*CC*HT;
    float psum[4] = {0,0,0,0};
    float pmax[4] = {-FLT_MAX,-FLT_MAX,-FLT_MAX,-FLT_MAX};
    #pragma unroll
    for (int o8 = 0; o8 < 8; o8++) {
        int o = oy*8 + o8;
        float g = __ldg(gam + o), be = __ldg(bet + o);
        float r[4];
        #pragma unroll
        for (int k = 0; k < 4; k++) {
            r[k] = fmaxf(fmaf(rr[o8][k], g, be), 0.f);   // bn + relu
        }
        if (branch) {
            #pragma unroll
            for (int k = 0; k < 4; k++) { psum[k] += r[k]; pmax[k] = fmaxf(pmax[k], r[k]); }
        } else {
            float ps = 0.f, pm = -FLT_MAX;
            #pragma unroll
            for (int k = 0; k < 4; k++)
                if (gp0 + k < HT) { ps += r[k]; pm = fmaxf(pm, r[k]); }
            #pragma unroll
            for (int s = 16; s > 0; s >>= 1) {
                ps += __shfl_xor_sync(0xffffffffu, ps, s);
                pm = fmaxf(pm, __shfl_xor_sync(0xffffffffu, pm, s));
            }
            if (px == 0) {
                cps[((size_t)b*NBLK + blockIdx.x)*CC + o] = ps;
                cpm[((size_t)b*NBLK + blockIdx.x)*CC + o] = pm;
            }
        }
        if (full) {
            *(float4*)(outb + (size_t)o*HT + gp0) = make_float4(r[0],r[1],r[2],r[3]);
        } else {
            for (int k = 0; k < 4; k++) if (gp0+k < HT) outb[(size_t)o*HT + gp0 + k] = r[k];
        }
    }

    if (branch) {
        int p = px*4;
        #pragma unroll
        for (int k = 0; k < 4; k++) { sredS[oy*128 + p + k] = psum[k]; sredM[oy*128 + p + k] = pmax[k]; }
        __syncthreads();
        if (tid < 128) {
            float s = 0.f, m = -FLT_MAX;
            #pragma unroll
            for (int g = 0; g < 8; g++) { s += sredS[g*128 + tid]; m = fmaxf(m, sredM[g*128 + tid]); }
            int gp = pos0 + tid;
            if (gp < HT) {
                sp[(size_t)b*2*HT + gp]      = s*(1.f/CC);
                sp[(size_t)b*2*HT + HT + gp] = m;
            }
        }
    }
}

// ============ fused dw1x3(b1^2 * a_ch) + pointwise + bn + sigmoid (f32x2) ====
// dw1x3 computed from 3 L1-cached coalesced global reads; single sync; 48KB smem.
__launch_bounds__(256, 3)
__global__ void cb_fused(const float* __restrict__ b1, const float* __restrict__ ach,
                         const float* __restrict__ dw, const float* __restrict__ Wt,
                         const float* __restrict__ gamma, const float* __restrict__ beta,
                         float* __restrict__ out)
{
    extern __shared__ float sm[];
    float* sWt = sm;               // 4096
    float* sx  = sm + 4096;        // 8192

    int tid = threadIdx.x;
    int px = tid & 31, oy = tid >> 5;
    int b = blockIdx.y;
    int pos0 = blockIdx.x * 128;
    const float* inb = b1 + (size_t)b*CC*HT;

    #pragma unroll
    for (int i = tid; i < 1024; i += 256)
        ((float4*)sWt)[i] = ((const float4*)Wt)[i];

    for (int i = tid; i < 8192; i += 256) {
        int c = i >> 7, j = i & 127;
        int gp = pos0 + j;
        float r = 0.f;
        if (gp < HT) {
            int t = gp - (gp/TT)*TT;
            float a  = __ldg(ach + b*CC + c);
            float w0 = __ldg(dw + c*3), w1 = __ldg(dw + c*3 + 1), w2 = __ldg(dw + c*3 + 2);
            const float* row = inb + (size_t)c*HT;
            float v0 = row[gp];
            r = w1 * (v0*v0*a);
            if (t > 0)    { float vm = row[gp-1]; r = fmaf(w0, vm*vm*a, r); }
            if (t < TT-1) { float vp = row[gp+1]; r = fmaf(w2, vp*vp*a, r); }
        }
        sx[c*128 + j] = r;
    }
    __syncthreads();

    float rr[8][4];
    gemm_core(sWt, sx, px, oy, rr);

    int gp0 = pos0 + px*4;
    bool full = (gp0 + 3) < HT;
    float* outb = out + (size_t)b*CC*HT;
    #pragma unroll
    for (int o8 = 0; o8 < 8; o8++) {
        int o = oy*8 + o8;
        float g = __ldg(gamma + o), be = __ldg(beta + o);
        float r[4];
        #pragma unroll
        for (int k = 0; k < 4; k++) {
            r[k] = fmaf(rr[o8][k], g, be);
            r[k] = 1.f/(1.f + expf(-r[k]));
        }
        if (full) *(float4*)(outb + (size_t)o*HT + gp0) = make_float4(r[0],r[1],r[2],r[3]);
        else for (int k = 0; k < 4; k++) if (gp0+k < HT) outb[(size_t)o*HT + gp0 + k] = r[k];
    }
}

// ========= dual depthwise 5x5: 64t x 16h tiles, 4 outputs/thread, f32x2 ========
__launch_bounds__(256)
__global__ void dw5_dual2(const float* __restrict__ in, const float* __restrict__ w0,
                          const float* __restrict__ w1,
                          float* __restrict__ out0, float* __restrict__ out1, int rev)
{
    int bc = blockIdx.z;
    int c  = bc & (CC-1);
    __shared__ float tile[20*68];
    __shared__ u64 swp[25];
    int t0 = blockIdx.x*64 - 2;
    int h0 = blockIdx.y*16 - 2;
    const float* base = in + (size_t)bc*HT;
    int tid = threadIdx.x;

    if (tid < 25) swp[tid] = pack2(__ldg(w0 + c*25 + tid), __ldg(w1 + c*25 + tid));

    for (int i = tid; i < 20*68; i += 256) {
        int hh = i / 68, tt = i - hh*68;
        int h = h0 + hh, t = t0 + tt;
        float v = 0.f;
        if (h >= 0 && h < HH && t >= 0 && t < TT) {
            int tr = rev ? (TT-1-t) : t;
            v = base[h*TT + tr];
        }
        tile[i] = v;
    }
    __syncthreads();

    int tt0 = (tid & 15)*4;
    int hh  = tid >> 4;
    int tg  = blockIdx.x*64 + tt0;
    int hg  = blockIdx.y*16 + hh;

    u64 acc[4] = {0ull, 0ull, 0ull, 0ull};
    #pragma unroll
    for (int kh = 0; kh < 5; kh++) {
        const float* row = tile + (hh + kh)*68 + tt0;
        float4 ra = *(const float4*)(row);
        float4 rb = *(const float4*)(row + 4);
        float r[8] = {ra.x, ra.y, ra.z, ra.w, rb.x, rb.y, rb.z, rb.w};
        #pragma unroll
        for (int kw = 0; kw < 5; kw++) {
            u64 w = swp[kh*5 + kw];
            acc[0] = ffma2(w, bcast2(r[kw+0]), acc[0]);
            acc[1] = ffma2(w, bcast2(r[kw+1]), acc[1]);
            acc[2] = ffma2(w, bcast2(r[kw+2]), acc[2]);
            acc[3] = ffma2(w, bcast2(r[kw+3]), acc[3]);
        }
    }

    if (hg >= HH) return;
    float o0[4], o1[4];
    #pragma unroll
    for (int k = 0; k < 4; k++) unpack2(acc[k], o0[k], o1[k]);
    size_t obase = (size_t)bc*HT + hg*TT + tg;
    if (tg + 3 < TT) {
        *(float4*)(out0 + obase) = make_float4(o0[0], o0[1], o0[2], o0[3]);
        *(float4*)(out1 + obase) = make_float4(o1[0], o1[1], o1[2], o1[3]);
    } else {
        for (int k = 0; k < 4; k++) if (tg + k < TT) {
            out0[obase + k] = o0[k];
            out1[obase + k] = o1[k];
        }
    }
}

// ---------------- channel attention: reduce partials + MLP ---------------------
__global__ void chan_attn2(const float* __restrict__ cps, const float* __restrict__ cpm,
                           const float* __restrict__ w1, const float* __restrict__ w2,
                           float* __restrict__ a)
{
    int b = blockIdx.x, tid = threadIdx.x;
    __shared__ float sa[CC], smx[CC], hs[MIDC];
    int c = tid >> 2, q = tid & 3;
    float s = 0.f, m = -FLT_MAX;
    for (int k = q; k < NBLK; k += 4) {
        s += cps[((size_t)b*NBLK + k)*CC + c];
        m = fmaxf(m, cpm[((size_t)b*NBLK + k)*CC + c]);
    }
    s += __shfl_xor_sync(0xffffffffu, s, 1);
    m = fmaxf(m, __shfl_xor_sync(0xffffffffu, m, 1));
    s += __shfl_xor_sync(0xffffffffu, s, 2);
    m = fmaxf(m, __shfl_xor_sync(0xffffffffu, m, 2));
    if (q == 0) { sa[c] = s*(1.f/(float)HT); smx[c] = m; }
    __syncthreads();
    if (tid < MIDC) {
        float ha = 0.f, hm = 0.f;
        for (int k = 0; k < CC; k++) {
            ha = fmaf(sa[k],  w1[tid*CC + k], ha);
            hm = fmaf(smx[k], w1[tid*CC + k], hm);
        }
        hs[tid] = fmaxf(ha, 0.f) + fmaxf(hm, 0.f);
    }
    __syncthreads();
    if (tid < CC) {
        float acc = 0.f;
        #pragma unroll
        for (int j = 0; j < MIDC; j++) acc = fmaf(hs[j], w2[tid*MIDC + j], acc);
        a[b*CC + tid] = 1.f/(1.f + expf(-acc));
    }
}

// ---------------- spatial attention 7x7 conv (2ch->1) + sigmoid -----------------
__global__ void spat_conv(const float* __restrict__ sp, const float* __restrict__ w,
                          float* __restrict__ asp)
{
    int t = blockIdx.x*32 + threadIdx.x;
    int h = blockIdx.y*8  + threadIdx.y;
    int b = blockIdx.z;
    if (t >= TT || h >= HH) return;
    float acc = 0.f;
    #pragma unroll
    for (int ci = 0; ci < 2; ci++) {
        const float* base = sp + ((size_t)b*2 + ci)*HT;
        #pragma unroll
        for (int kh = 0; kh < 7; kh++) {
            int hh = h + kh - 3;
            if (hh < 0 || hh >= HH) continue;
            #pragma unroll
            for (int kw = 0; kw < 7; kw++) {
                int tt = t + kw - 3;
                if (tt < 0 || tt >= TT) continue;
                acc = fmaf(base[hh*TT + tt], __ldg(&w[ci*49 + kh*7 + kw]), acc);
            }
        }
    }
    asp[(size_t)b*HT + h*TT + t] = 1.f/(1.f + expf(-acc));
}

// ---------------- SSM precompute: log-depth chain via A^8 ----------------------
#define SSM_SMEM ((5152 + TT*SSZ)*4)
__launch_bounds__(256)
__global__ void ssm_pre3(const float* __restrict__ A, const float* __restrict__ Bv,
                         const float* __restrict__ Cm, float* __restrict__ sc)
{
    extern __shared__ float sm[];
    float* sA  = sm;
    float* sM  = sm + 1024;
    float* sT  = sm + 2048;
    float* sC  = sm + 3072;
    float* sVV = sm + 5120;
    float* sS  = sm + 5152;

    int half = blockIdx.x;
    A  += half*SSZ*SSZ;
    Bv += half*SSZ;
    Cm += half*SSZ*CC;
    sc += (size_t)half*TT*CC;

    int tid = threadIdx.x;
    int wid = tid >> 5, lid = tid & 31;

    for (int i = tid; i < 1024; i += 256) sA[i] = A[i];
    for (int i = tid; i < 2048; i += 256) sC[i] = Cm[i];
    __syncthreads();
    for (int i = tid; i < 1024; i += 256) {
        int r = i >> 5, c = i & 31;
        float acc = 0.f;
        #pragma unroll
        for (int k = 0; k < 32; k++) acc = fmaf(sA[r*32+k], sA[k*32+c], acc);
        sT[i] = acc;
    }
    __syncthreads();
    for (int i = tid; i < 1024; i += 256) {
        int r = i >> 5, c = i & 31;
        float acc = 0.f;
        #pragma unroll
        for (int k = 0; k < 32; k++) acc = fmaf(sT[r*32+k], sT[k*32+c], acc);
        sM[i] = acc;
    }
    __syncthreads();
    for (int i = tid; i < 1024; i += 256) {
        int r = i >> 5, c = i & 31;
        float acc = 0.f;
        #pragma unroll
        for (int k = 0; k < 32; k++) acc = fmaf(sM[r*32+k], sM[k*32+c], acc);
        sT[i] = acc;
    }
    __syncthreads();

    if (wid == 0) {
        float bv = Bv[lid];
        float Arow[32];
        #pragma unroll
        for (int j = 0; j < 32; j++) Arow[j] = sA[lid*32 + j];
        float x = bv;
        sS[lid] = x;
        #pragma unroll
        for (int k = 1; k < 8; k++) {
            float nx = bv;
            #pragma unroll
            for (int j = 0; j < 32; j++) nx = fmaf(__shfl_sync(0xffffffffu, x, j), Arow[j], nx);
            x = nx;
            sS[k*32 + lid] = x;
        }
        sVV[lid] = x;
    }
    __syncthreads();

    {
        float Mrow[32];
        #pragma unroll
        for (int j = 0; j < 32; j++) Mrow[j] = sT[lid*32 + j];
        float vv = sVV[lid];
        float x = sS[wid*32 + lid];
        for (int n = 1; n < 50; n++) {
            float p0 = vv, p1 = 0.f, p2 = 0.f, p3 = 0.f;
            #pragma unroll
            for (int j = 0; j < 8; j++) {
                p0 = fmaf(__shfl_sync(0xffffffffu, x, j),    Mrow[j],    p0);
                p1 = fmaf(__shfl_sync(0xffffffffu, x, j+8),  Mrow[j+8],  p1);
                p2 = fmaf(__shfl_sync(0xffffffffu, x, j+16), Mrow[j+16], p2);
                p3 = fmaf(__shfl_sync(0xffffffffu, x, j+24), Mrow[j+24], p3);
            }
            x = (p0 + p1) + (p2 + p3);
            sS[(wid + 8*n)*32 + lid] = x;
        }
    }
    __syncthreads();

    for (int i = tid; i < TT*CC; i += 256) {
        int t = i >> 6, c = i & 63;
        float acc = 0.f;
        #pragma unroll
        for (int k = 0; k < 32; k++) acc = fmaf(sS[t*32 + k], sC[k*64 + c], acc);
        sc[i] = acc;
    }
}

// ---------------- fused: residual-gelu + channel-LN + spatial gate --------------
__launch_bounds__(256)
__global__ void final_fuse(const float* __restrict__ cb, const float* __restrict__ b2,
                           const float* __restrict__ asp, const float* __restrict__ sc,
                           const float* __restrict__ Dv, const float* __restrict__ lg,
                           const float* __restrict__ lb, float* __restrict__ out, int revout)
{
    __shared__ float sred[256];
    __shared__ float smu[32], srs[32];
    __shared__ float sD[CC], slg[CC], slb[CC];

    int tid = threadIdx.x;
    int px = tid & 31, cy = tid >> 5;
    int b = blockIdx.y;
    int pos = blockIdx.x*32 + px;
    if (tid < CC) { sD[tid] = Dv[tid]; slg[tid] = lg[tid]; slb[tid] = lb[tid]; }
    __syncthreads();

    int t = pos % TT, h = pos / TT;
    const float* cbb = cb + (size_t)b*CC*HT + pos;
    const float* b2b = b2 + (size_t)b*CC*HT + pos;
    const float* scp = sc + t*CC;

    float val[8], bvv[8];
    float sum = 0.f;
    #pragma unroll
    for (int k = 0; k < 8; k++) {
        int c = cy*8 + k;
        int c2 = (h - 2*c) & (CC-1);
        float x = cbb[(size_t)c*HT];
        bvv[k] = b2b[(size_t)c*HT];
        float pre = __ldg(scp + c2) + x*sD[c2];
        float gel = 0.5f*pre*(1.f + erff(pre*0.70710678118654752f));
        val[k] = x + gel;
        sum += val[k];
    }
    sred[cy*32 + px] = sum;
    __syncthreads();
    if (cy == 0) {
        float tot = 0.f;
        #pragma unroll
        for (int g = 0; g < 8; g++) tot += sred[g*32 + px];
        smu[px] = tot*(1.f/CC);
    }
    __syncthreads();
    float mu = smu[px];
    float vp = 0.f;
    #pragma unroll
    for (int k = 0; k < 8; k++) { float d = val[k]-mu; vp = fmaf(d, d, vp); }
    __syncthreads();
    sred[cy*32 + px] = vp;
    __syncthreads();
    if (cy == 0) {
        float tot = 0.f;
        #pragma unroll
        for (int g = 0; g < 8; g++) tot += sred[g*32 + px];
        srs[px] = rsqrtf(tot*(1.f/CC) + 1e-5f);
    }
    __syncthreads();
    float rstd = srs[px];
    float aspv = asp[(size_t)b*HT + pos];
    int opos = revout ? (h*TT + (TT-1-t)) : pos;
    float* outb = out + (size_t)b*CC*HT + opos;
    #pragma unroll
    for (int k = 0; k < 8; k++) {
        int c = cy*8 + k;
        float y = (val[k]-mu)*rstd*slg[c] + slb[c];
        float sb = 1.f/(1.f + expf(-(bvv[k]*bvv[k]*aspv)));
        outb[(size_t)c*HT] = y*sb;
    }
}

// ---------------- host orchestration --------------------------------------------
#define PW_SMEM   49152
#define PWD_SMEM  57344
#define CB_SMEM   49152

static void run_half(const float* in, float* outb, int rev,
                     const float* dwdw, const float* Wt_b1, const float* Wt_b2,
                     const float* dwg, const float* dwb,
                     const float* caw1, const float* caw2, const float* saw,
                     const float* d1dw, const float* Wt_cb, const float* d1g, const float* d1b,
                     const float* sD, const float* lng, const float* lnb,
                     const float* psc_half,
                     float* bufB, float* bufC, float* bufD,
                     float* pach, float* pcps, float* pcpm, float* psp, float* pasp)
{
    dim3 g5((TT+63)/64, (HH+15)/16, BB*CC);
    dw5_dual2<<<g5, 256>>>(in, dwdw, dwdw + CC*25, bufB, bufC, rev);

    // both branch pointwise mixes in one launch (z = branch)
    pw_dual<<<dim3(NBLK, BB, 2), 256, PWD_SMEM>>>(bufB, bufC, Wt_b1, Wt_b2,
                                                  dwg, dwb, bufB, bufC,
                                                  psp, pcps, pcpm);

    chan_attn2<<<BB, 256>>>(pcps, pcpm, caw1, caw2, pach);

    cb_fused<<<dim3(NBLK, BB), 256, CB_SMEM>>>(bufB, pach, d1dw, Wt_cb, d1g, d1b, bufD);

    spat_conv<<<dim3((TT+31)/32, (HH+7)/8, BB), dim3(32, 8)>>>(psp, saw, pasp);

    final_fuse<<<dim3(HT/32, BB), 256>>>(bufD, bufC, pasp, psc_half, sD, lng, lnb, outb, rev);
}

extern "C" void kernel_launch(void* const* d_in, const int* in_sizes, int n_in,
                              void* d_out, int out_size)
{
    const float* x       = (const float*)d_in[0];
    const float* in_w    = (const float*)d_in[1];
    const float* dw2d_dw = (const float*)d_in[2];
    const float* dw2d_pw = (const float*)d_in[3];
    const float* dw2d_g  = (const float*)d_in[4];
    const float* dw2d_b  = (const float*)d_in[5];
    const float* ca_w1   = (const float*)d_in[6];
    const float* ca_w2   = (const float*)d_in[7];
    const float* sa_w    = (const float*)d_in[8];
    const float* dw1d_dw = (const float*)d_in[9];
    const float* dw1d_pw = (const float*)d_in[10];
    const float* dw1d_g  = (const float*)d_in[11];
    const float* dw1d_b  = (const float*)d_in[12];
    const float* ssm_A   = (const float*)d_in[13];
    const float* ssm_B   = (const float*)d_in[14];
    const float* ssm_C   = (const float*)d_in[15];
    const float* ssm_D   = (const float*)d_in[16];
    const float* ln_g    = (const float*)d_in[17];
    const float* ln_b    = (const float*)d_in[18];
    const float* out_w   = (const float*)d_in[19];
    const float* out_g   = (const float*)d_in[20];
    const float* out_b   = (const float*)d_in[21];

    float *pA, *pB, *pC, *pD, *pE, *pach, *pcps, *pcpm, *psp, *pasp, *psc, *pWt;
    cudaGetSymbolAddress((void**)&pA,   g_A);
    cudaGetSymbolAddress((void**)&pB,   g_B2);
    cudaGetSymbolAddress((void**)&pC,   g_C2);
    cudaGetSymbolAddress((void**)&pD,   g_D2);
    cudaGetSymbolAddress((void**)&pE,   g_E2);
    cudaGetSymbolAddress((void**)&pach, g_ach);
    cudaGetSymbolAddress((void**)&pcps, g_cps);
    cudaGetSymbolAddress((void**)&pcpm, g_cpm);
    cudaGetSymbolAddress((void**)&psp,  g_sp);
    cudaGetSymbolAddress((void**)&pasp, g_asp);
    cudaGetSymbolAddress((void**)&psc,  g_sc);
    cudaGetSymbolAddress((void**)&pWt,  g_Wt);

    cudaFuncSetAttribute(pw2<0>,   cudaFuncAttributeMaxDynamicSharedMemorySize, PW_SMEM);
    cudaFuncSetAttribute(pw2<1>,   cudaFuncAttributeMaxDynamicSharedMemorySize, PW_SMEM);
    cudaFuncSetAttribute(pw_dual,  cudaFuncAttributeMaxDynamicSharedMemorySize, PWD_SMEM);
    cudaFuncSetAttribute(cb_fused, cudaFuncAttributeMaxDynamicSharedMemorySize, CB_SMEM);
    cudaFuncSetAttribute(ssm_pre3, cudaFuncAttributeMaxDynamicSharedMemorySize, SSM_SMEM);

    // transpose all 8 pointwise weight matrices; SSM tables
    wtrans<<<8, 256>>>(in_w, dw2d_pw, dw1d_pw, out_w, pWt);
    ssm_pre3<<<2, 256, SSM_SMEM>>>(ssm_A, ssm_B, ssm_C, psc);

    dim3 gp(NBLK, BB);

    // input pointwise mix
    pw2<0><<<gp, 256, PW_SMEM>>>(x, pWt, nullptr, nullptr, pA);

    // half 1
    run_half(pA, pE, 0,
             dw2d_dw, pWt + 1*CC*CC, pWt + 2*CC*CC, dw2d_g, dw2d_b,
             ca_w1, ca_w2, sa_w,
             dw1d_dw, pWt + 5*CC*CC, dw1d_g, dw1d_b,
             ssm_D, ln_g, ln_b, psc,
             pB, pC, pD, pach, pcps, pcpm, psp, pasp);

    // half 2 (reversed read, reversed write-back)
    run_half(pE, pA, 1,
             dw2d_dw + 2*CC*25, pWt + 3*CC*CC, pWt + 4*CC*CC, dw2d_g + 2*CC, dw2d_b + 2*CC,
             ca_w1 + MIDC*CC, ca_w2 + CC*MIDC, sa_w + 2*49,
             dw1d_dw + CC*3, pWt + 6*CC*CC, dw1d_g + CC, dw1d_b + CC,
             ssm_D + CC, ln_g + CC, ln_b + CC, psc + TT*CC,
             pB, pC, pD, pach, pcps, pcpm, psp, pasp);

    // output pointwise mix + bn + relu
    pw2<1><<<gp, 256, PW_SMEM>>>(pA, pWt + 7*CC*CC, out_g, out_b, (float*)d_out);
}

// round 11
// speedup vs baseline: 1.5915x; 1.1134x over previous
#include <cuda_runtime.h>
#include <math.h>
#include <float.h>

#define BB 8
#define CC 64
#define HH 62
#define TT 400
#define HT (HH*TT)            // 24800
#define NTOT (BB*CC*HT)       // 12697600
#define SSZ 32
#define MIDC 4
#define NBLK 194              // ceil(HT/128)

typedef unsigned long long u64;

__device__ __forceinline__ u64 ffma2(u64 a, u64 b, u64 c) {
    u64 d;
    asm("fma.rn.f32x2 %0, %1, %2, %3;" : "=l"(d) : "l"(a), "l"(b), "l"(c));
    return d;
}
__device__ __forceinline__ u64 bcast2(float x) {
    u64 r;
    asm("mov.b64 %0, {%1, %1};" : "=l"(r) : "f"(x));
    return r;
}
__device__ __forceinline__ u64 pack2(float lo, float hi) {
    u64 r;
    asm("mov.b64 %0, {%1, %2};" : "=l"(r) : "f"(lo), "f"(hi));
    return r;
}
__device__ __forceinline__ void unpack2(u64 v, float& lo, float& hi) {
    asm("mov.b64 {%0, %1}, %2;" : "=f"(lo), "=f"(hi) : "l"(v));
}

// ---------------- scratch (device globals) ----------------
__device__ float g_A[NTOT];
__device__ float g_B2[NTOT];
__device__ float g_C2[NTOT];
__device__ float g_D2[NTOT];
__device__ float g_E2[NTOT];
__device__ float g_ach[BB*CC];
__device__ float g_cps[BB*NBLK*CC];
__device__ float g_cpm[BB*NBLK*CC];
__device__ float g_sp[BB*2*HT];
__device__ float g_asp[BB*HT];
__device__ float g_sc[2*TT*CC];
__device__ float g_Wt[8*CC*CC];       // transposed weights [m][c][o]

// ---------------- transpose all 8 pointwise weight matrices --------------------
__global__ void wtrans(const float* __restrict__ in_w, const float* __restrict__ dwpw,
                       const float* __restrict__ d1pw, const float* __restrict__ out_w,
                       float* __restrict__ Wt)
{
    int m = blockIdx.x;
    const float* src = (m == 0) ? in_w
                     : (m < 5)  ? dwpw + (m-1)*CC*CC
                     : (m < 7)  ? d1pw + (m-5)*CC*CC
                                : out_w;
    for (int i = threadIdx.x; i < CC*CC; i += 256) {
        int o = i >> 6, c = i & 63;
        Wt[m*CC*CC + c*CC + o] = src[i];
    }
}

// ============ register-blocked pointwise 64x64 mix, f32x2 over out-pairs ======
template<int ACT, bool SPSTATS, bool CPARTS>
__launch_bounds__(256, 3)
__global__ void pw2(const float* __restrict__ in, const float* __restrict__ Wt,
                    const float* __restrict__ gamma, const float* __restrict__ beta,
                    float* __restrict__ out, float* __restrict__ sp,
                    float* __restrict__ cps, float* __restrict__ cpm)
{
    extern __shared__ float sm[];
    float* sWt = sm;                   // 4096 floats, [c][o]
    float* sx  = sm + 4096;            // 64*128 floats
    float* sredS = sm + 4096 + 8192;   // 8*128 (SPSTATS)
    float* sredM = sredS + 1024;

    int tid = threadIdx.x;
    int px = tid & 31, oy = tid >> 5;
    int b = blockIdx.y;
    int pos0 = blockIdx.x * 128;
    const float* inb = in + (size_t)b*CC*HT;

    #pragma unroll
    for (int i = tid; i < 1024; i += 256)
        ((float4*)sWt)[i] = ((const float4*)Wt)[i];

    #pragma unroll
    for (int i = tid; i < 2048; i += 256) {
        int c = i >> 5, j = i & 31;
        int gp = pos0 + j*4;
        float4 v = make_float4(0.f,0.f,0.f,0.f);
        if (gp + 3 < HT) {
            v = *(const float4*)(inb + (size_t)c*HT + gp);
        } else {
            float tmp[4] = {0,0,0,0};
            for (int k = 0; k < 4; k++) if (gp+k < HT) tmp[k] = inb[(size_t)c*HT + gp + k];
            v = make_float4(tmp[0],tmp[1],tmp[2],tmp[3]);
        }
        *(float4*)(sx + c*128 + j*4) = v;
    }
    __syncthreads();

    int p = px*4;
    u64 acc2[4][4];
    #pragma unroll
    for (int q = 0; q < 4; q++)
        #pragma unroll
        for (int k = 0; k < 4; k++) acc2[q][k] = 0ull;

    #pragma unroll
    for (int c4 = 0; c4 < 16; c4++) {
        #pragma unroll
        for (int cc = 0; cc < 4; cc++) {
            int c = c4*4 + cc;
            float4 xv = *(const float4*)(sx + c*128 + p);
            u64 xp0 = bcast2(xv.x), xp1 = bcast2(xv.y);
            u64 xp2 = bcast2(xv.z), xp3 = bcast2(xv.w);
            const ulonglong2* wrow = (const ulonglong2*)(sWt + c*64 + oy*8);
            ulonglong2 wa = wrow[0];
            ulonglong2 wb = wrow[1];
            acc2[0][0] = ffma2(wa.x, xp0, acc2[0][0]);
            acc2[0][1] = ffma2(wa.x, xp1, acc2[0][1]);
            acc2[0][2] = ffma2(wa.x, xp2, acc2[0][2]);
            acc2[0][3] = ffma2(wa.x, xp3, acc2[0][3]);
            acc2[1][0] = ffma2(wa.y, xp0, acc2[1][0]);
            acc2[1][1] = ffma2(wa.y, xp1, acc2[1][1]);
            acc2[1][2] = ffma2(wa.y, xp2, acc2[1][2]);
            acc2[1][3] = ffma2(wa.y, xp3, acc2[1][3]);
            acc2[2][0] = ffma2(wb.x, xp0, acc2[2][0]);
            acc2[2][1] = ffma2(wb.x, xp1, acc2[2][1]);
            acc2[2][2] = ffma2(wb.x, xp2, acc2[2][2]);
            acc2[2][3] = ffma2(wb.x, xp3, acc2[2][3]);
            acc2[3][0] = ffma2(wb.y, xp0, acc2[3][0]);
            acc2[3][1] = ffma2(wb.y, xp1, acc2[3][1]);
            acc2[3][2] = ffma2(wb.y, xp2, acc2[3][2]);
            acc2[3][3] = ffma2(wb.y, xp3, acc2[3][3]);
        }
    }

    float rr[8][4];
    #pragma unroll
    for (int q = 0; q < 4; q++)
        #pragma unroll
        for (int k = 0; k < 4; k++)
            unpack2(acc2[q][k], rr[2*q][k], rr[2*q+1][k]);

    int gp0 = pos0 + p;
    bool full = (gp0 + 3) < HT;
    float* outb = out + (size_t)b*CC*HT;
    float psum[4] = {0,0,0,0};
    float pmax[4] = {-FLT_MAX,-FLT_MAX,-FLT_MAX,-FLT_MAX};
    #pragma unroll
    for (int o8 = 0; o8 < 8; o8++) {
        int o = oy*8 + o8;
        float r[4];
        #pragma unroll
        for (int k = 0; k < 4; k++) r[k] = rr[o8][k];
        if (gamma) {
            float g = __ldg(gamma + o), be = __ldg(beta + o);
            #pragma unroll
            for (int k = 0; k < 4; k++) r[k] = fmaf(r[k], g, be);
        }
        #pragma unroll
        for (int k = 0; k < 4; k++) {
            if (ACT == 1) r[k] = fmaxf(r[k], 0.f);
            if (ACT == 2) r[k] = 1.f/(1.f + expf(-r[k]));
        }
        if (SPSTATS) {
            #pragma unroll
            for (int k = 0; k < 4; k++) { psum[k] += r[k]; pmax[k] = fmaxf(pmax[k], r[k]); }
        }
        if (CPARTS) {
            float ps = 0.f, pm = -FLT_MAX;
            #pragma unroll
            for (int k = 0; k < 4; k++)
                if (gp0 + k < HT) { ps += r[k]; pm = fmaxf(pm, r[k]); }
            #pragma unroll
            for (int s = 16; s > 0; s >>= 1) {
                ps += __shfl_xor_sync(0xffffffffu, ps, s);
                pm = fmaxf(pm, __shfl_xor_sync(0xffffffffu, pm, s));
            }
            if (px == 0) {
                cps[((size_t)b*NBLK + blockIdx.x)*CC + o] = ps;
                cpm[((size_t)b*NBLK + blockIdx.x)*CC + o] = pm;
            }
        }
        if (full) {
            *(float4*)(outb + (size_t)o*HT + gp0) = make_float4(r[0],r[1],r[2],r[3]);
        } else {
            for (int k = 0; k < 4; k++) if (gp0+k < HT) outb[(size_t)o*HT + gp0 + k] = r[k];
        }
    }

    if (SPSTATS) {
        #pragma unroll
        for (int k = 0; k < 4; k++) { sredS[oy*128 + p + k] = psum[k]; sredM[oy*128 + p + k] = pmax[k]; }
        __syncthreads();
        if (tid < 128) {
            float s = 0.f, m = -FLT_MAX;
            #pragma unroll
            for (int g = 0; g < 8; g++) { s += sredS[g*128 + tid]; m = fmaxf(m, sredM[g*128 + tid]); }
            int gp = pos0 + tid;
            if (gp < HT) {
                sp[(size_t)b*2*HT + gp]      = s*(1.f/CC);
                sp[(size_t)b*2*HT + HT + gp] = m;
            }
        }
    }
}

// ============ fused dw1x3(b1^2 * a_ch) + pointwise + bn + sigmoid (f32x2) ===
// smem: sraw[64][132] (33792B) unioned with sWt (16KB); sx @8448 floats.
__launch_bounds__(256, 3)
__global__ void cb_fused(const float* __restrict__ b1, const float* __restrict__ ach,
                         const float* __restrict__ dw, const float* __restrict__ Wt,
                         const float* __restrict__ gamma, const float* __restrict__ beta,
                         float* __restrict__ out)
{
    extern __shared__ float sm[];
    float* sraw = sm;              // 64*132
    float* sWt  = sm;              // union (after conv phase), 4096 floats
    float* sx   = sm + 8448;       // 64*128

    int tid = threadIdx.x;
    int px = tid & 31, oy = tid >> 5;
    int b = blockIdx.y;
    int pos0 = blockIdx.x * 128;
    const float* inb = b1 + (size_t)b*CC*HT;

    for (int i = tid; i < 64*130; i += 256) {
        int c = i / 130, j = i - c*130;
        int gp = pos0 - 1 + j;
        float v = 0.f;
        if (gp >= 0 && gp < HT) v = inb[(size_t)c*HT + gp];
        float a = __ldg(ach + b*CC + c);
        sraw[c*132 + j] = v*v*a;
    }
    __syncthreads();

    for (int i = tid; i < 8192; i += 256) {
        int c = i >> 7, j = i & 127;
        int gp = pos0 + j;
        float r = 0.f;
        if (gp < HT) {
            int t = gp - (gp/TT)*TT;
            float w0 = __ldg(dw + c*3), w1 = __ldg(dw + c*3 + 1), w2 = __ldg(dw + c*3 + 2);
            r = w1 * sraw[c*132 + j + 1];
            if (t > 0)    r = fmaf(w0, sraw[c*132 + j],     r);
            if (t < TT-1) r = fmaf(w2, sraw[c*132 + j + 2], r);
        }
        sx[c*128 + j] = r;
    }
    __syncthreads();

    #pragma unroll
    for (int i = tid; i < 1024; i += 256)
        ((float4*)sWt)[i] = ((const float4*)Wt)[i];
    __syncthreads();

    int p = px*4;
    u64 acc2[4][4];
    #pragma unroll
    for (int q = 0; q < 4; q++)
        #pragma unroll
        for (int k = 0; k < 4; k++) acc2[q][k] = 0ull;

    #pragma unroll
    for (int c4 = 0; c4 < 16; c4++) {
        #pragma unroll
        for (int cc = 0; cc < 4; cc++) {
            int c = c4*4 + cc;
            float4 xv = *(const float4*)(sx + c*128 + p);
            u64 xp0 = bcast2(xv.x), xp1 = bcast2(xv.y);
            u64 xp2 = bcast2(xv.z), xp3 = bcast2(xv.w);
            const ulonglong2* wrow = (const ulonglong2*)(sWt + c*64 + oy*8);
            ulonglong2 wa = wrow[0];
            ulonglong2 wb = wrow[1];
            acc2[0][0] = ffma2(wa.x, xp0, acc2[0][0]);
            acc2[0][1] = ffma2(wa.x, xp1, acc2[0][1]);
            acc2[0][2] = ffma2(wa.x, xp2, acc2[0][2]);
            acc2[0][3] = ffma2(wa.x, xp3, acc2[0][3]);
            acc2[1][0] = ffma2(wa.y, xp0, acc2[1][0]);
            acc2[1][1] = ffma2(wa.y, xp1, acc2[1][1]);
            acc2[1][2] = ffma2(wa.y, xp2, acc2[1][2]);
            acc2[1][3] = ffma2(wa.y, xp3, acc2[1][3]);
            acc2[2][0] = ffma2(wb.x, xp0, acc2[2][0]);
            acc2[2][1] = ffma2(wb.x, xp1, acc2[2][1]);
            acc2[2][2] = ffma2(wb.x, xp2, acc2[2][2]);
            acc2[2][3] = ffma2(wb.x, xp3, acc2[2][3]);
            acc2[3][0] = ffma2(wb.y, xp0, acc2[3][0]);
            acc2[3][1] = ffma2(wb.y, xp1, acc2[3][1]);
            acc2[3][2] = ffma2(wb.y, xp2, acc2[3][2]);
            acc2[3][3] = ffma2(wb.y, xp3, acc2[3][3]);
        }
    }

    float rr[8][4];
    #pragma unroll
    for (int q = 0; q < 4; q++)
        #pragma unroll
        for (int k = 0; k < 4; k++)
            unpack2(acc2[q][k], rr[2*q][k], rr[2*q+1][k]);

    int gp0 = pos0 + p;
    bool full = (gp0 + 3) < HT;
    float* outb = out + (size_t)b*CC*HT;
    #pragma unroll
    for (int o8 = 0; o8 < 8; o8++) {
        int o = oy*8 + o8;
        float g = __ldg(gamma + o), be = __ldg(beta + o);
        float r[4];
        #pragma unroll
        for (int k = 0; k < 4; k++) {
            r[k] = fmaf(rr[o8][k], g, be);
            r[k] = 1.f/(1.f + expf(-r[k]));
        }
        if (full) *(float4*)(outb + (size_t)o*HT + gp0) = make_float4(r[0],r[1],r[2],r[3]);
        else for (int k = 0; k < 4; k++) if (gp0+k < HT) outb[(size_t)o*HT + gp0 + k] = r[k];
    }
}

// ========= dual depthwise 5x5: 64t x 16h tiles, 4 outputs/thread, f32x2 ========
// Broadcasts hoisted out of kw loop: 8 MOVs per row instead of 20.
__launch_bounds__(256)
__global__ void dw5_dual2(const float* __restrict__ in, const float* __restrict__ w0,
                          const float* __restrict__ w1,
                          float* __restrict__ out0, float* __restrict__ out1, int rev)
{
    int bc = blockIdx.z;
    int c  = bc & (CC-1);
    __shared__ float tile[20*68];
    __shared__ u64 swp[25];
    int t0 = blockIdx.x*64 - 2;
    int h0 = blockIdx.y*16 - 2;
    const float* base = in + (size_t)bc*HT;
    int tid = threadIdx.x;

    if (tid < 25) swp[tid] = pack2(__ldg(w0 + c*25 + tid), __ldg(w1 + c*25 + tid));

    for (int i = tid; i < 20*68; i += 256) {
        int hh = i / 68, tt = i - hh*68;
        int h = h0 + hh, t = t0 + tt;
        float v = 0.f;
        if (h >= 0 && h < HH && t >= 0 && t < TT) {
            int tr = rev ? (TT-1-t) : t;
            v = base[h*TT + tr];
        }
        tile[i] = v;
    }
    __syncthreads();

    int tt0 = (tid & 15)*4;
    int hh  = tid >> 4;
    int tg  = blockIdx.x*64 + tt0;
    int hg  = blockIdx.y*16 + hh;

    u64 acc[4] = {0ull, 0ull, 0ull, 0ull};
    #pragma unroll
    for (int kh = 0; kh < 5; kh++) {
        const float* row = tile + (hh + kh)*68 + tt0;
        float4 ra = *(const float4*)(row);
        float4 rb = *(const float4*)(row + 4);
        u64 br[8];
        br[0] = bcast2(ra.x); br[1] = bcast2(ra.y);
        br[2] = bcast2(ra.z); br[3] = bcast2(ra.w);
        br[4] = bcast2(rb.x); br[5] = bcast2(rb.y);
        br[6] = bcast2(rb.z); br[7] = bcast2(rb.w);
        #pragma unroll
        for (int kw = 0; kw < 5; kw++) {
            u64 w = swp[kh*5 + kw];
            acc[0] = ffma2(w, br[kw+0], acc[0]);
            acc[1] = ffma2(w, br[kw+1], acc[1]);
            acc[2] = ffma2(w, br[kw+2], acc[2]);
            acc[3] = ffma2(w, br[kw+3], acc[3]);
        }
    }

    if (hg >= HH) return;
    float o0[4], o1[4];
    #pragma unroll
    for (int k = 0; k < 4; k++) unpack2(acc[k], o0[k], o1[k]);
    size_t obase = (size_t)bc*HT + hg*TT + tg;
    if (tg + 3 < TT) {
        *(float4*)(out0 + obase) = make_float4(o0[0], o0[1], o0[2], o0[3]);
        *(float4*)(out1 + obase) = make_float4(o1[0], o1[1], o1[2], o1[3]);
    } else {
        for (int k = 0; k < 4; k++) if (tg + k < TT) {
            out0[obase + k] = o0[k];
            out1[obase + k] = o1[k];
        }
    }
}

// ---------------- channel attention: reduce partials + MLP ---------------------
__global__ void chan_attn2(const float* __restrict__ cps, const float* __restrict__ cpm,
                           const float* __restrict__ w1, const float* __restrict__ w2,
                           float* __restrict__ a)
{
    int b = blockIdx.x, tid = threadIdx.x;
    __shared__ float sa[CC], smx[CC], hs[MIDC];
    int c = tid >> 2, q = tid & 3;
    float s = 0.f, m = -FLT_MAX;
    for (int k = q; k < NBLK; k += 4) {
        s += cps[((size_t)b*NBLK + k)*CC + c];
        m = fmaxf(m, cpm[((size_t)b*NBLK + k)*CC + c]);
    }
    s += __shfl_xor_sync(0xffffffffu, s, 1);
    m = fmaxf(m, __shfl_xor_sync(0xffffffffu, m, 1));
    s += __shfl_xor_sync(0xffffffffu, s, 2);
    m = fmaxf(m, __shfl_xor_sync(0xffffffffu, m, 2));
    if (q == 0) { sa[c] = s*(1.f/(float)HT); smx[c] = m; }
    __syncthreads();
    if (tid < MIDC) {
        float ha = 0.f, hm = 0.f;
        for (int k = 0; k < CC; k++) {
            ha = fmaf(sa[k],  w1[tid*CC + k], ha);
            hm = fmaf(smx[k], w1[tid*CC + k], hm);
        }
        hs[tid] = fmaxf(ha, 0.f) + fmaxf(hm, 0.f);
    }
    __syncthreads();
    if (tid < CC) {
        float acc = 0.f;
        #pragma unroll
        for (int j = 0; j < MIDC; j++) acc = fmaf(hs[j], w2[tid*MIDC + j], acc);
        a[b*CC + tid] = 1.f/(1.f + expf(-acc));
    }
}

// ---------------- spatial attention 7x7 conv (2ch->1) + sigmoid -----------------
__global__ void spat_conv(const float* __restrict__ sp, const float* __restrict__ w,
                          float* __restrict__ asp)
{
    int t = blockIdx.x*32 + threadIdx.x;
    int h = blockIdx.y*8  + threadIdx.y;
    int b = blockIdx.z;
    if (t >= TT || h >= HH) return;
    float acc = 0.f;
    #pragma unroll
    for (int ci = 0; ci < 2; ci++) {
        const float* base = sp + ((size_t)b*2 + ci)*HT;
        #pragma unroll
        for (int kh = 0; kh < 7; kh++) {
            int hh = h + kh - 3;
            if (hh < 0 || hh >= HH) continue;
            #pragma unroll
            for (int kw = 0; kw < 7; kw++) {
                int tt = t + kw - 3;
                if (tt < 0 || tt >= TT) continue;
                acc = fmaf(base[hh*TT + tt], __ldg(&w[ci*49 + kh*7 + kw]), acc);
            }
        }
    }
    asp[(size_t)b*HT + h*TT + t] = 1.f/(1.f + expf(-acc));
}

// ---------------- SSM precompute: log-depth chain via A^8 ----------------------
#define SSM_SMEM ((5152 + TT*SSZ)*4)
__launch_bounds__(256)
__global__ void ssm_pre3(const float* __restrict__ A, const float* __restrict__ Bv,
                         const float* __restrict__ Cm, float* __restrict__ sc)
{
    extern __shared__ float sm[];
    float* sA  = sm;
    float* sM  = sm + 1024;
    float* sT  = sm + 2048;
    float* sC  = sm + 3072;
    float* sVV = sm + 5120;
    float* sS  = sm + 5152;

    int half = blockIdx.x;
    A  += half*SSZ*SSZ;
    Bv += half*SSZ;
    Cm += half*SSZ*CC;
    sc += (size_t)half*TT*CC;

    int tid = threadIdx.x;
    int wid = tid >> 5, lid = tid & 31;

    for (int i = tid; i < 1024; i += 256) sA[i] = A[i];
    for (int i = tid; i < 2048; i += 256) sC[i] = Cm[i];
    __syncthreads();
    for (int i = tid; i < 1024; i += 256) {
        int r = i >> 5, c = i & 31;
        float acc = 0.f;
        #pragma unroll
        for (int k = 0; k < 32; k++) acc = fmaf(sA[r*32+k], sA[k*32+c], acc);
        sT[i] = acc;
    }
    __syncthreads();
    for (int i = tid; i < 1024; i += 256) {
        int r = i >> 5, c = i & 31;
        float acc = 0.f;
        #pragma unroll
        for (int k = 0; k < 32; k++) acc = fmaf(sT[r*32+k], sT[k*32+c], acc);
        sM[i] = acc;
    }
    __syncthreads();
    for (int i = tid; i < 1024; i += 256) {
        int r = i >> 5, c = i & 31;
        float acc = 0.f;
        #pragma unroll
        for (int k = 0; k < 32; k++) acc = fmaf(sM[r*32+k], sM[k*32+c], acc);
        sT[i] = acc;
    }
    __syncthreads();

    if (wid == 0) {
        float bv = Bv[lid];
        float Arow[32];
        #pragma unroll
        for (int j = 0; j < 32; j++) Arow[j] = sA[lid*32 + j];
        float x = bv;
        sS[lid] = x;
        #pragma unroll
        for (int k = 1; k < 8; k++) {
            float nx = bv;
            #pragma unroll
            for (int j = 0; j < 32; j++) nx = fmaf(__shfl_sync(0xffffffffu, x, j), Arow[j], nx);
            x = nx;
            sS[k*32 + lid] = x;
        }
        sVV[lid] = x;
    }
    __syncthreads();

    {
        float Mrow[32];
        #pragma unroll
        for (int j = 0; j < 32; j++) Mrow[j] = sT[lid*32 + j];
        float vv = sVV[lid];
        float x = sS[wid*32 + lid];
        for (int n = 1; n < 50; n++) {
            float p0 = vv, p1 = 0.f, p2 = 0.f, p3 = 0.f;
            #pragma unroll
            for (int j = 0; j < 8; j++) {
                p0 = fmaf(__shfl_sync(0xffffffffu, x, j),    Mrow[j],    p0);
                p1 = fmaf(__shfl_sync(0xffffffffu, x, j+8),  Mrow[j+8],  p1);
                p2 = fmaf(__shfl_sync(0xffffffffu, x, j+16), Mrow[j+16], p2);
                p3 = fmaf(__shfl_sync(0xffffffffu, x, j+24), Mrow[j+24], p3);
            }
            x = (p0 + p1) + (p2 + p3);
            sS[(wid + 8*n)*32 + lid] = x;
        }
    }
    __syncthreads();

    for (int i = tid; i < TT*CC; i += 256) {
        int t = i >> 6, c = i & 63;
        float acc = 0.f;
        #pragma unroll
        for (int k = 0; k < 32; k++) acc = fmaf(sS[t*32 + k], sC[k*64 + c], acc);
        sc[i] = acc;
    }
}

// ---------------- fused: residual-gelu + channel-LN + spatial gate --------------
__launch_bounds__(256)
__global__ void final_fuse(const float* __restrict__ cb, const float* __restrict__ b2,
                           const float* __restrict__ asp, const float* __restrict__ sc,
                           const float* __restrict__ Dv, const float* __restrict__ lg,
                           const float* __restrict__ lb, float* __restrict__ out, int revout)
{
    __shared__ float sred[256];
    __shared__ float smu[32], srs[32];
    __shared__ float sD[CC], slg[CC], slb[CC];

    int tid = threadIdx.x;
    int px = tid & 31, cy = tid >> 5;
    int b = blockIdx.y;
    int pos = blockIdx.x*32 + px;
    if (tid < CC) { sD[tid] = Dv[tid]; slg[tid] = lg[tid]; slb[tid] = lb[tid]; }
    __syncthreads();

    int t = pos % TT, h = pos / TT;
    const float* cbb = cb + (size_t)b*CC*HT + pos;
    const float* b2b = b2 + (size_t)b*CC*HT + pos;
    const float* scp = sc + t*CC;

    float val[8], bvv[8];
    float sum = 0.f;
    #pragma unroll
    for (int k = 0; k < 8; k++) {
        int c = cy*8 + k;
        int c2 = (h - 2*c) & (CC-1);
        float x = cbb[(size_t)c*HT];
        bvv[k] = b2b[(size_t)c*HT];
        float pre = __ldg(scp + c2) + x*sD[c2];
        float gel = 0.5f*pre*(1.f + erff(pre*0.70710678118654752f));
        val[k] = x + gel;
        sum += val[k];
    }
    sred[cy*32 + px] = sum;
    __syncthreads();
    if (cy == 0) {
        float tot = 0.f;
        #pragma unroll
        for (int g = 0; g < 8; g++) tot += sred[g*32 + px];
        smu[px] = tot*(1.f/CC);
    }
    __syncthreads();
    float mu = smu[px];
    float vp = 0.f;
    #pragma unroll
    for (int k = 0; k < 8; k++) { float d = val[k]-mu; vp = fmaf(d, d, vp); }
    __syncthreads();
    sred[cy*32 + px] = vp;
    __syncthreads();
    if (cy == 0) {
        float tot = 0.f;
        #pragma unroll
        for (int g = 0; g < 8; g++) tot += sred[g*32 + px];
        srs[px] = rsqrtf(tot*(1.f/CC) + 1e-5f);
    }
    __syncthreads();
    float rstd = srs[px];
    float aspv = asp[(size_t)b*HT + pos];
    int opos = revout ? (h*TT + (TT-1-t)) : pos;
    float* outb = out + (size_t)b*CC*HT + opos;
    #pragma unroll
    for (int k = 0; k < 8; k++) {
        int c = cy*8 + k;
        float y = (val[k]-mu)*rstd*slg[c] + slb[c];
        float sb = 1.f/(1.f + expf(-(bvv[k]*bvv[k]*aspv)));
        outb[(size_t)c*HT] = y*sb;
    }
}

// ---------------- host orchestration --------------------------------------------
#define PW_SMEM   49152
#define PWS_SMEM  57344
#define CB_SMEM   66560

static void run_half(const float* in, float* outb, int rev,
                     const float* dwdw, const float* Wt_b1, const float* Wt_b2,
                     const float* dwg, const float* dwb,
                     const float* caw1, const float* caw2, const float* saw,
                     const float* d1dw, const float* Wt_cb, const float* d1g, const float* d1b,
                     const float* sD, const float* lng, const float* lnb,
                     const float* psc_half,
                     float* bufB, float* bufC, float* bufD,
                     float* pach, float* pcps, float* pcpm, float* psp, float* pasp)
{
    dim3 g5((TT+63)/64, (HH+15)/16, BB*CC);
    dw5_dual2<<<g5, 256>>>(in, dwdw, dwdw + CC*25, bufB, bufC, rev);

    dim3 gp(NBLK, BB);
    pw2<1,false,true ><<<gp, 256, PW_SMEM>>>(bufB, Wt_b1, dwg,    dwb,    bufB, nullptr, pcps, pcpm);
    pw2<1,true ,false><<<gp, 256, PWS_SMEM>>>(bufC, Wt_b2, dwg+CC, dwb+CC, bufC, psp, nullptr, nullptr);

    chan_attn2<<<BB, 256>>>(pcps, pcpm, caw1, caw2, pach);

    cb_fused<<<gp, 256, CB_SMEM>>>(bufB, pach, d1dw, Wt_cb, d1g, d1b, bufD);

    spat_conv<<<dim3((TT+31)/32, (HH+7)/8, BB), dim3(32, 8)>>>(psp, saw, pasp);

    final_fuse<<<dim3(HT/32, BB), 256>>>(bufD, bufC, pasp, psc_half, sD, lng, lnb, outb, rev);
}

extern "C" void kernel_launch(void* const* d_in, const int* in_sizes, int n_in,
                              void* d_out, int out_size)
{
    const float* x       = (const float*)d_in[0];
    const float* in_w    = (const float*)d_in[1];
    const float* dw2d_dw = (const float*)d_in[2];
    const float* dw2d_pw = (const float*)d_in[3];
    const float* dw2d_g  = (const float*)d_in[4];
    const float* dw2d_b  = (const float*)d_in[5];
    const float* ca_w1   = (const float*)d_in[6];
    const float* ca_w2   = (const float*)d_in[7];
    const float* sa_w    = (const float*)d_in[8];
    const float* dw1d_dw = (const float*)d_in[9];
    const float* dw1d_pw = (const float*)d_in[10];
    const float* dw1d_g  = (const float*)d_in[11];
    const float* dw1d_b  = (const float*)d_in[12];
    const float* ssm_A   = (const float*)d_in[13];
    const float* ssm_B   = (const float*)d_in[14];
    const float* ssm_C   = (const float*)d_in[15];
    const float* ssm_D   = (const float*)d_in[16];
    const float* ln_g    = (const float*)d_in[17];
    const float* ln_b    = (const float*)d_in[18];
    const float* out_w   = (const float*)d_in[19];
    const float* out_g   = (const float*)d_in[20];
    const float* out_b   = (const float*)d_in[21];

    float *pA, *pB, *pC, *pD, *pE, *pach, *pcps, *pcpm, *psp, *pasp, *psc, *pWt;
    cudaGetSymbolAddress((void**)&pA,   g_A);
    cudaGetSymbolAddress((void**)&pB,   g_B2);
    cudaGetSymbolAddress((void**)&pC,   g_C2);
    cudaGetSymbolAddress((void**)&pD,   g_D2);
    cudaGetSymbolAddress((void**)&pE,   g_E2);
    cudaGetSymbolAddress((void**)&pach, g_ach);
    cudaGetSymbolAddress((void**)&pcps, g_cps);
    cudaGetSymbolAddress((void**)&pcpm, g_cpm);
    cudaGetSymbolAddress((void**)&psp,  g_sp);
    cudaGetSymbolAddress((void**)&pasp, g_asp);
    cudaGetSymbolAddress((void**)&psc,  g_sc);
    cudaGetSymbolAddress((void**)&pWt,  g_Wt);

    cudaFuncSetAttribute(pw2<0,false,false>, cudaFuncAttributeMaxDynamicSharedMemorySize, PW_SMEM);
    cudaFuncSetAttribute(pw2<1,false,false>, cudaFuncAttributeMaxDynamicSharedMemorySize, PW_SMEM);
    cudaFuncSetAttribute(pw2<1,false,true >, cudaFuncAttributeMaxDynamicSharedMemorySize, PW_SMEM);
    cudaFuncSetAttribute(pw2<1,true ,false>, cudaFuncAttributeMaxDynamicSharedMemorySize, PWS_SMEM);
    cudaFuncSetAttribute(cb_fused,           cudaFuncAttributeMaxDynamicSharedMemorySize, CB_SMEM);
    cudaFuncSetAttribute(ssm_pre3,           cudaFuncAttributeMaxDynamicSharedMemorySize, SSM_SMEM);

    // transpose all 8 pointwise weight matrices; SSM tables
    wtrans<<<8, 256>>>(in_w, dw2d_pw, dw1d_pw, out_w, pWt);
    ssm_pre3<<<2, 256, SSM_SMEM>>>(ssm_A, ssm_B, ssm_C, psc);

    dim3 gp(NBLK, BB);

    // input pointwise mix
    pw2<0,false,false><<<gp, 256, PW_SMEM>>>(x, pWt, nullptr, nullptr, pA, nullptr, nullptr, nullptr);

    // half 1
    run_half(pA, pE, 0,
             dw2d_dw, pWt + 1*CC*CC, pWt + 2*CC*CC, dw2d_g, dw2d_b,
             ca_w1, ca_w2, sa_w,
             dw1d_dw, pWt + 5*CC*CC, dw1d_g, dw1d_b,
             ssm_D, ln_g, ln_b, psc,
             pB, pC, pD, pach, pcps, pcpm, psp, pasp);

    // half 2 (reversed read, reversed write-back)
    run_half(pE, pA, 1,
             dw2d_dw + 2*CC*25, pWt + 3*CC*CC, pWt + 4*CC*CC, dw2d_g + 2*CC, dw2d_b + 2*CC,
             ca_w1 + MIDC*CC, ca_w2 + CC*MIDC, sa_w + 2*49,
             dw1d_dw + CC*3, pWt + 6*CC*CC, dw1d_g + CC, dw1d_b + CC,
             ssm_D + CC, ln_g + CC, ln_b + CC, psc + TT*CC,
             pB, pC, pD, pach, pcps, pcpm, psp, pasp);

    // output pointwise mix + bn + relu
    pw2<1,false,false><<<gp, 256, PW_SMEM>>>(pA, pWt + 7*CC*CC, out_g, out_b, (float*)d_out, nullptr, nullptr, nullptr);
}